// round 13
// baseline (speedup 1.0000x reference)
#include <cuda_runtime.h>
#include <cuda_bf16.h>
#include <cstdint>

// Problem constants
#define B_  2
#define S_  2048
#define D_  2560
#define H_  32
#define HD_ 80
#define RD_ 32

constexpr int M_ROWS = B_ * S_;       // 4096
constexpr int QKV_N  = 3 * D_;        // 7680

// Scratch (no allocation allowed -> __device__ globals)
__device__ float g_qkv[(size_t)M_ROWS * QKV_N];   // fp32 qkv from GEMM1
__device__ float g_rope_tab[S_ * 32];             // [s][0..15]=cos, [16..31]=sin
// bf16 hi/lo split operands for GEMMs
__device__ __align__(256) __nv_bfloat16 g_ahi[(size_t)M_ROWS * D_];   // x / ctx
__device__ __align__(256) __nv_bfloat16 g_alo[(size_t)M_ROWS * D_];
__device__ __align__(256) __nv_bfloat16 g_whi[(size_t)QKV_N  * D_];
__device__ __align__(256) __nv_bfloat16 g_wlo[(size_t)QKV_N  * D_];
__device__ __align__(256) __nv_bfloat16 g_ohi[(size_t)D_ * D_];
__device__ __align__(256) __nv_bfloat16 g_olo[(size_t)D_ * D_];
// head-major pre-split q/k/v: [b][h][s][80]
constexpr size_t HM_SZ = (size_t)B_ * H_ * S_ * HD_;
__device__ __align__(256) __nv_bfloat16 g_qh[HM_SZ], g_ql[HM_SZ];
__device__ __align__(256) __nv_bfloat16 g_kh[HM_SZ], g_kl[HM_SZ];
__device__ __align__(256) __nv_bfloat16 g_vh[HM_SZ], g_vl[HM_SZ];

// ---------------------------------------------------------------------------
// PTX helpers
// ---------------------------------------------------------------------------
__device__ __forceinline__ uint32_t smem_u32(const void* p) {
    uint32_t a;
    asm("{ .reg .u64 t; cvta.to.shared.u64 t, %1; cvt.u32.u64 %0, t; }"
        : "=r"(a) : "l"(p));
    return a;
}
__device__ __forceinline__ void ldsm4u(uint32_t* r, uint32_t addr) {
    asm volatile("ldmatrix.sync.aligned.m8n8.x4.shared.b16 {%0,%1,%2,%3}, [%4];"
                 : "=r"(r[0]), "=r"(r[1]), "=r"(r[2]), "=r"(r[3]) : "r"(addr));
}
__device__ __forceinline__ void ldsm4t(uint32_t* r, uint32_t addr) {
    asm volatile("ldmatrix.sync.aligned.m8n8.x4.trans.shared.b16 {%0,%1,%2,%3}, [%4];"
                 : "=r"(r[0]), "=r"(r[1]), "=r"(r[2]), "=r"(r[3]) : "r"(addr));
}
__device__ __forceinline__ void mma16816(float* c, const uint32_t* a,
                                         uint32_t b0, uint32_t b1)
{
    asm volatile(
        "mma.sync.aligned.m16n8k16.row.col.f32.bf16.bf16.f32 "
        "{%0,%1,%2,%3}, {%4,%5,%6,%7}, {%8,%9}, {%0,%1,%2,%3};"
        : "+f"(c[0]), "+f"(c[1]), "+f"(c[2]), "+f"(c[3])
        : "r"(a[0]), "r"(a[1]), "r"(a[2]), "r"(a[3]), "r"(b0), "r"(b1));
}
__device__ __forceinline__ void cp_async16(uint32_t dst, const void* src) {
    asm volatile("cp.async.cg.shared.global [%0], [%1], 16;"
                 :: "r"(dst), "l"((unsigned long long)__cvta_generic_to_global(src)));
}
#define CP_COMMIT() asm volatile("cp.async.commit_group;" ::: "memory")

#define SWZ64(o) ((o) ^ (((o) >> 3) & 0x30))

__device__ __forceinline__ float ex2f(float x) {
    float r;
    asm("ex2.approx.f32 %0, %1;" : "=f"(r) : "f"(x));
    return r;
}

__device__ __forceinline__ void split2(float x, float y, uint32_t& hi, uint32_t& lo) {
    __nv_bfloat162 h = __floats2bfloat162_rn(x, y);
    float2 f = __bfloat1622float2(h);
    __nv_bfloat162 l = __floats2bfloat162_rn(x - f.x, y - f.y);
    hi = *(uint32_t*)&h;
    lo = *(uint32_t*)&l;
}
__device__ __forceinline__ void split4(float4 v, uint2& hi, uint2& lo) {
    split2(v.x, v.y, hi.x, lo.x);
    split2(v.z, v.w, hi.y, lo.y);
}

// ---------------------------------------------------------------------------
// fp32 -> bf16 hi/lo split (elementwise, same layout)
// ---------------------------------------------------------------------------
__global__ void cvt_split(const float4* __restrict__ in, uint2* __restrict__ hi,
                          uint2* __restrict__ lo, int n4)
{
    int i = blockIdx.x * blockDim.x + threadIdx.x;
    if (i >= n4) return;
    uint2 h, l;
    split4(in[i], h, l);
    hi[i] = h;
    lo[i] = l;
}

// ---------------------------------------------------------------------------
// RoPE cos/sin table (fp64 angle path, bit-matching the reference).
// ---------------------------------------------------------------------------
__global__ void rope_table_kernel()
{
    const int t = blockIdx.x * blockDim.x + threadIdx.x;   // 0..32767
    const int i = t & 15;
    const int s = t >> 4;
    const double inv = exp2(-(double)i * (13.287712379549449 / 16.0));
    const float ang  = (float)((double)s * inv);
    g_rope_tab[s * 32 + i]      = cosf(ang);
    g_rope_tab[s * 32 + 16 + i] = sinf(ang);
}

// ---------------------------------------------------------------------------
// Fused RoPE(table) + split: qkv fp32 -> head-major bf16 hi/lo q/k/v.
// q pre-scaled by (1/sqrt(80)) * log2(e) -> attention softmax in exp2 domain.
// ---------------------------------------------------------------------------
__global__ void cvt_qkv(const float4* __restrict__ qkv4)
{
    int idx = blockIdx.x * blockDim.x + threadIdx.x;
    const int n4 = M_ROWS * QKV_N / 4;
    if (idx >= n4) return;
    const int col4 = idx % (QKV_N / 4);
    const int rowm = idx / (QKV_N / 4);      // b*S + s
    const int col  = col4 * 4;
    const int part = col / D_;
    const int win  = col % D_;
    const int h    = win / HD_;
    const int d    = win % HD_;
    const int b    = rowm >> 11;
    const int s    = rowm & (S_ - 1);

    float4 v = qkv4[idx];

    if (part < 2 && d < RD_) {
        const bool first = (d < 16);
        const int  i     = first ? d : d - 16;
        const float4 cv  = *(const float4*)&g_rope_tab[s * 32 + i];
        const float4 sv  = *(const float4*)&g_rope_tab[s * 32 + 16 + i];
        const float4 ov  = qkv4[idx + (first ? 4 : -4)];
        if (first) {
            v.x = v.x * cv.x - ov.x * sv.x;
            v.y = v.y * cv.y - ov.y * sv.y;
            v.z = v.z * cv.z - ov.z * sv.z;
            v.w = v.w * cv.w - ov.w * sv.w;
        } else {
            v.x = ov.x * sv.x + v.x * cv.x;
            v.y = ov.y * sv.y + v.y * cv.y;
            v.z = ov.z * sv.z + v.z * cv.z;
            v.w = ov.w * sv.w + v.w * cv.w;
        }
    }
    if (part == 0) {   // fold softmax scale AND log2(e) into q
        const float scale = 0.11180339887498949f * 1.4426950408889634f;
        v.x *= scale; v.y *= scale; v.z *= scale; v.w *= scale;
    }

    uint2 hi, lo;
    split4(v, hi, lo);
    const size_t dst = (((size_t)(b * H_ + h)) * S_ + s) * HD_ + d;
    __nv_bfloat16 *ph, *pl;
    if (part == 0)      { ph = g_qh; pl = g_ql; }
    else if (part == 1) { ph = g_kh; pl = g_kl; }
    else                { ph = g_vh; pl = g_vl; }
    *(uint2*)&ph[dst] = hi;
    *(uint2*)&pl[dst] = lo;
}

// ---------------------------------------------------------------------------
// HMMA bf16x3 NT GEMM (verified, unchanged).
// ---------------------------------------------------------------------------
constexpr int GEMM_SMEM = 3 * 32768;

__global__ __launch_bounds__(256, 2)
void gemm_hmma(const __nv_bfloat16* __restrict__ Ahi, const __nv_bfloat16* __restrict__ Alo,
               const __nv_bfloat16* __restrict__ Bhi, const __nv_bfloat16* __restrict__ Blo,
               const float* __restrict__ bias, float* __restrict__ C,
               int M, int N, int K)
{
    extern __shared__ __align__(1024) char gsm[];
    const uint32_t sb = smem_u32(gsm);
    const int tid  = threadIdx.x;
    const int lane = tid & 31;
    const int wid  = tid >> 5;
    const int wm0  = (wid & 3) * 32;
    const int wn0  = (wid >> 2) * 64;
    const int bm   = blockIdx.y * 128;
    const int bn   = blockIdx.x * 128;
    const int lr   = lane & 7;
    const int g    = lane >> 3;

    const __nv_bfloat16* s0 = Ahi + (size_t)bm * K;
    const __nv_bfloat16* s1 = Alo + (size_t)bm * K;
    const __nv_bfloat16* s2 = Bhi + (size_t)bn * K;
    const __nv_bfloat16* s3 = Blo + (size_t)bn * K;

    float acc[2][8][4] = {};

    auto load_stage = [&](int s) {
        const uint32_t st = sb + (uint32_t)(s % 3) * 32768;
        #pragma unroll
        for (int it = 0; it < 8; ++it) {
            const int tile = it >> 1;
            const int idx  = tid + (it & 1) * 256;
            const int row  = idx >> 2;
            const int c    = idx & 3;
            const __nv_bfloat16* base =
                (tile == 0) ? s0 : (tile == 1) ? s1 : (tile == 2) ? s2 : s3;
            const __nv_bfloat16* gp = base + (size_t)row * K + s * 32 + c * 8;
            cp_async16(st + tile * 8192 + SWZ64((uint32_t)(row * 64 + c * 16)), gp);
        }
        CP_COMMIT();
    };

    const int nst = K >> 5;
    load_stage(0);
    load_stage(1);

    for (int s = 0; s < nst; ++s) {
        if (s + 1 < nst)
            asm volatile("cp.async.wait_group 1;" ::: "memory");
        else
            asm volatile("cp.async.wait_group 0;" ::: "memory");
        __syncthreads();
        if (s + 2 < nst) load_stage(s + 2);

        const uint32_t st = sb + (uint32_t)(s % 3) * 32768;
        #pragma unroll
        for (int ks = 0; ks < 2; ++ks) {
            uint32_t ah[2][4], al[2][4];
            #pragma unroll
            for (int mi = 0; mi < 2; ++mi) {
                const uint32_t ro = (uint32_t)((wm0 + mi * 16 + lr + (g & 1) * 8) * 64
                                               + ks * 32 + (g >> 1) * 16);
                ldsm4u(ah[mi], st + SWZ64(ro));
                ldsm4u(al[mi], st + 8192 + SWZ64(ro));
            }
            #pragma unroll
            for (int np = 0; np < 4; ++np) {
                const uint32_t ro = (uint32_t)((wn0 + np * 16 + lr + (g >> 1) * 8) * 64
                                               + ks * 32 + (g & 1) * 16);
                uint32_t bh[4], bl[4];
                ldsm4u(bh, st + 16384 + SWZ64(ro));
                ldsm4u(bl, st + 24576 + SWZ64(ro));
                #pragma unroll
                for (int half = 0; half < 2; ++half) {
                    const int ni = np * 2 + half;
                    #pragma unroll
                    for (int mi = 0; mi < 2; ++mi) {
                        mma16816(acc[mi][ni], ah[mi], bh[half * 2], bh[half * 2 + 1]);
                        mma16816(acc[mi][ni], ah[mi], bl[half * 2], bl[half * 2 + 1]);
                        mma16816(acc[mi][ni], al[mi], bh[half * 2], bh[half * 2 + 1]);
                    }
                }
            }
        }
    }

    #pragma unroll
    for (int ni = 0; ni < 8; ++ni) {
        const int col = bn + wn0 + ni * 8 + (lane & 3) * 2;
        const float2 bv = *(const float2*)&bias[col];
        #pragma unroll
        for (int mi = 0; mi < 2; ++mi) {
            const int row = bm + wm0 + mi * 16 + (lane >> 2);
            *(float2*)&C[(size_t)row * N + col] =
                make_float2(acc[mi][ni][0] + bv.x, acc[mi][ni][1] + bv.y);
            *(float2*)&C[(size_t)(row + 8) * N + col] =
                make_float2(acc[mi][ni][2] + bv.x, acc[mi][ni][3] + bv.y);
        }
    }
}

// ---------------------------------------------------------------------------
// Causal flash attention, HMMA bf16x3, 256-row Q tiles, 512 threads
// (16 warps x 16 rows -> 4 warps/SMSP), 2 KV buffers, exp2-domain softmax.
// Q-lo fragments reloaded from smem per tile to stay under the 128-reg cap.
// smem: Qhi 45056 | Qlo 45056 | KV buf0 45056 | KV buf1 45056 = 180224 B.
// ---------------------------------------------------------------------------
constexpr int ATTN_SMEM = 4 * 45056;   // 180224

__global__ __launch_bounds__(512, 1)
void attn_tc(const __nv_bfloat16* __restrict__ qh_g, const __nv_bfloat16* __restrict__ ql_g,
             const __nv_bfloat16* __restrict__ kh_g, const __nv_bfloat16* __restrict__ kl_g,
             const __nv_bfloat16* __restrict__ vh_g, const __nv_bfloat16* __restrict__ vl_g,
             __nv_bfloat16* __restrict__ chi, __nv_bfloat16* __restrict__ clo)
{
    extern __shared__ __align__(1024) char smc[];
    const uint32_t sb = smem_u32(smc);
    const int qt   = gridDim.x - 1 - blockIdx.x;   // big tiles first
    const int h    = blockIdx.y;
    const int b    = blockIdx.z;
    const int tid  = threadIdx.x;
    const int lane = tid & 31;
    const int wid  = tid >> 5;          // 0..15
    const int wm   = wid * 16;          // warp's q-row base within 256-row tile
    const int lr   = lane & 7;
    const int g    = lane >> 3;

    const size_t hb = ((size_t)(b * H_ + h)) * S_ * HD_;

    // ---- stage Q: hi at 0, lo at 45056 (256 rows x 176B) ----
    for (int t = tid; t < 5120; t += 512) {
        const int arr = t / 2560, rem = t % 2560;
        const int row = rem / 10, c = rem % 10;
        const __nv_bfloat16* src = (arr ? ql_g : qh_g) + hb
                                   + (size_t)(qt * 256 + row) * HD_ + c * 8;
        cp_async16(sb + (uint32_t)(arr * 45056 + row * 176 + c * 16), src);
    }
    CP_COMMIT();
    asm volatile("cp.async.wait_group 0;" ::: "memory");
    __syncthreads();

    // Q-hi fragments persistent in regs; Q-lo reloaded from smem per tile.
    const uint32_t qro = (uint32_t)((wm + lr + (g & 1) * 8) * 176 + (g >> 1) * 16);
    uint32_t qh[5][4];
    #pragma unroll
    for (int ks = 0; ks < 5; ++ks)
        ldsm4u(qh[ks], sb + qro + ks * 32);
    const uint32_t qlbase = sb + 45056 + qro;
    // (Q smem region is never overwritten; no extra sync needed)

    const uint32_t KVB = sb + 90112;
    auto load_kv = [&](int kt) {
        const uint32_t st = KVB + (uint32_t)(kt & 1) * 45056;
        const __nv_bfloat16* srcs[4] = { kh_g, kl_g, vh_g, vl_g };
        #pragma unroll
        for (int it = 0; it < 5; ++it) {
            const int t = tid + it * 512;            // 0..2559
            const int arr = t / 640, rem = t % 640;
            const int row = rem / 10, c = rem % 10;
            const __nv_bfloat16* src = srcs[arr] + hb
                                       + (size_t)(kt * 64 + row) * HD_ + c * 8;
            cp_async16(st + (uint32_t)(arr * 11264 + row * 176 + c * 16), src);
        }
        CP_COMMIT();
    };

    float o[10][4] = {};
    float mx0 = -1e30f, mx1 = -1e30f, l0 = 0.f, l1 = 0.f;
    const int nkt = 4 * qt + 4;

    const uint32_t krow = (uint32_t)(((lane >> 4) * 8 + lr) * 176 + ((lane >> 3) & 1) * 16);
    const uint32_t vrow = (uint32_t)((((lane >> 3) & 1) * 8 + lr) * 176 + (lane >> 4) * 16);

    load_kv(0);

    for (int kt = 0; kt < nkt; ++kt) {
        asm volatile("cp.async.wait_group 0;" ::: "memory");
        __syncthreads();
        if (kt + 1 < nkt) load_kv(kt + 1);   // writes other buffer; readers passed sync

        const bool active = (qt * 256 + wm + 15 >= kt * 64);
        if (active) {
            const uint32_t st = KVB + (uint32_t)(kt & 1) * 45056;

            // ---- scores S = Q K^T (bf16x3); ks outer so Q-lo loads once/ks ----
            float s[8][4];
            #pragma unroll
            for (int nb = 0; nb < 8; ++nb)
                s[nb][0] = s[nb][1] = s[nb][2] = s[nb][3] = 0.f;
            #pragma unroll
            for (int ks = 0; ks < 5; ++ks) {
                uint32_t ql4[4];
                ldsm4u(ql4, qlbase + ks * 32);
                #pragma unroll
                for (int nb2 = 0; nb2 < 4; ++nb2) {
                    float* sA = s[nb2 * 2];
                    float* sB = s[nb2 * 2 + 1];
                    const uint32_t ro = st + (uint32_t)(nb2 * 16 * 176) + krow + ks * 32;
                    uint32_t kh4[4], kl4[4];
                    ldsm4u(kh4, ro);
                    ldsm4u(kl4, ro + 11264);
                    mma16816(sA, qh[ks], kh4[0], kh4[1]);
                    mma16816(sA, qh[ks], kl4[0], kl4[1]);
                    mma16816(sA, ql4,    kh4[0], kh4[1]);
                    mma16816(sB, qh[ks], kh4[2], kh4[3]);
                    mma16816(sB, qh[ks], kl4[2], kl4[3]);
                    mma16816(sB, ql4,    kh4[2], kh4[3]);
                }
            }

            if (kt * 64 + 63 > qt * 256 + wm) {   // tile may cross diagonal for this warp
                const int r0 = qt * 256 + wm + (lane >> 2);
                #pragma unroll
                for (int nb = 0; nb < 8; ++nb) {
                    const int c0 = kt * 64 + nb * 8 + (lane & 3) * 2;
                    if (c0     > r0)     s[nb][0] = -1e30f;
                    if (c0 + 1 > r0)     s[nb][1] = -1e30f;
                    if (c0     > r0 + 8) s[nb][2] = -1e30f;
                    if (c0 + 1 > r0 + 8) s[nb][3] = -1e30f;
                }
            }

            // ---- online softmax (exp2 domain) ----
            float m0 = -1e30f, m1 = -1e30f;
            #pragma unroll
            for (int nb = 0; nb < 8; ++nb) {
                m0 = fmaxf(m0, fmaxf(s[nb][0], s[nb][1]));
                m1 = fmaxf(m1, fmaxf(s[nb][2], s[nb][3]));
            }
            m0 = fmaxf(m0, __shfl_xor_sync(0xffffffffu, m0, 1));
            m0 = fmaxf(m0, __shfl_xor_sync(0xffffffffu, m0, 2));
            m1 = fmaxf(m1, __shfl_xor_sync(0xffffffffu, m1, 1));
            m1 = fmaxf(m1, __shfl_xor_sync(0xffffffffu, m1, 2));
            const float mn0 = fmaxf(mx0, m0), mn1 = fmaxf(mx1, m1);
            const float corr0 = ex2f(mx0 - mn0), corr1 = ex2f(mx1 - mn1);
            mx0 = mn0; mx1 = mn1;
            float sum0 = 0.f, sum1 = 0.f;
            #pragma unroll
            for (int nb = 0; nb < 8; ++nb) {
                s[nb][0] = ex2f(s[nb][0] - mn0);
                s[nb][1] = ex2f(s[nb][1] - mn0);
                s[nb][2] = ex2f(s[nb][2] - mn1);
                s[nb][3] = ex2f(s[nb][3] - mn1);
                sum0 += s[nb][0] + s[nb][1];
                sum1 += s[nb][2] + s[nb][3];
            }
            sum0 += __shfl_xor_sync(0xffffffffu, sum0, 1);
            sum0 += __shfl_xor_sync(0xffffffffu, sum0, 2);
            sum1 += __shfl_xor_sync(0xffffffffu, sum1, 1);
            sum1 += __shfl_xor_sync(0xffffffffu, sum1, 2);
            l0 = l0 * corr0 + sum0;
            l1 = l1 * corr1 + sum1;
            #pragma unroll
            for (int nd = 0; nd < 10; ++nd) {
                o[nd][0] *= corr0; o[nd][1] *= corr0;
                o[nd][2] *= corr1; o[nd][3] *= corr1;
            }

            // ---- P -> bf16 hi/lo fragments ----
            uint32_t ph[4][4], pl[4][4];
            #pragma unroll
            for (int kb = 0; kb < 4; ++kb) {
                split2(s[2 * kb][0],     s[2 * kb][1],     ph[kb][0], pl[kb][0]);
                split2(s[2 * kb][2],     s[2 * kb][3],     ph[kb][1], pl[kb][1]);
                split2(s[2 * kb + 1][0], s[2 * kb + 1][1], ph[kb][2], pl[kb][2]);
                split2(s[2 * kb + 1][2], s[2 * kb + 1][3], ph[kb][3], pl[kb][3]);
            }

            // ---- O += P V (bf16x3), two nd blocks per ldsm.x4.trans ----
            #pragma unroll
            for (int nd2 = 0; nd2 < 5; ++nd2) {
                float* oA = o[nd2 * 2];
                float* oB = o[nd2 * 2 + 1];
                const uint32_t cbase = st + 22528 + (uint32_t)(nd2 * 32) + vrow;
                #pragma unroll
                for (int kb = 0; kb < 4; ++kb) {
                    uint32_t vh4[4], vl4[4];
                    const uint32_t ro = cbase + (uint32_t)(kb * 16 * 176);
                    ldsm4t(vh4, ro);
                    ldsm4t(vl4, ro + 11264);
                    mma16816(oA, ph[kb], vh4[0], vh4[1]);
                    mma16816(oA, ph[kb], vl4[0], vl4[1]);
                    mma16816(oA, pl[kb], vh4[0], vh4[1]);
                    mma16816(oB, ph[kb], vh4[2], vh4[3]);
                    mma16816(oB, ph[kb], vl4[2], vl4[3]);
                    mma16816(oB, pl[kb], vh4[2], vh4[3]);
                }
            }
        }
    }

    // Epilogue: normalize + write ctx as bf16 hi/lo (row-major [s][D])
    const float inv0 = 1.f / l0, inv1 = 1.f / l1;
    const int r0 = qt * 256 + wm + (lane >> 2);
    #pragma unroll
    for (int nd = 0; nd < 10; ++nd) {
        const int col = h * HD_ + nd * 8 + (lane & 3) * 2;
        uint32_t hi, lo;
        split2(o[nd][0] * inv0, o[nd][1] * inv0, hi, lo);
        *(uint32_t*)&chi[((size_t)(b * S_ + r0)) * D_ + col] = hi;
        *(uint32_t*)&clo[((size_t)(b * S_ + r0)) * D_ + col] = lo;
        split2(o[nd][2] * inv1, o[nd][3] * inv1, hi, lo);
        *(uint32_t*)&chi[((size_t)(b * S_ + r0 + 8)) * D_ + col] = hi;
        *(uint32_t*)&clo[((size_t)(b * S_ + r0 + 8)) * D_ + col] = lo;
    }
}

// ---------------------------------------------------------------------------
// Launch
// ---------------------------------------------------------------------------
extern "C" void kernel_launch(void* const* d_in, const int* in_sizes, int n_in,
                              void* d_out, int out_size)
{
    const float* x      = (const float*)d_in[0];
    const float* wqkv_w = (const float*)d_in[1];
    const float* wqkv_b = (const float*)d_in[2];
    const float* out_w  = (const float*)d_in[3];
    const float* out_b  = (const float*)d_in[4];
    float* out = (float*)d_out;

    float* qkv;
    __nv_bfloat16 *ahi, *alo, *whi, *wlo, *ohi, *olo;
    __nv_bfloat16 *qh, *ql, *kh, *kl, *vh, *vl;
    cudaGetSymbolAddress((void**)&qkv, g_qkv);
    cudaGetSymbolAddress((void**)&ahi, g_ahi);
    cudaGetSymbolAddress((void**)&alo, g_alo);
    cudaGetSymbolAddress((void**)&whi, g_whi);
    cudaGetSymbolAddress((void**)&wlo, g_wlo);
    cudaGetSymbolAddress((void**)&ohi, g_ohi);
    cudaGetSymbolAddress((void**)&olo, g_olo);
    cudaGetSymbolAddress((void**)&qh, g_qh);
    cudaGetSymbolAddress((void**)&ql, g_ql);
    cudaGetSymbolAddress((void**)&kh, g_kh);
    cudaGetSymbolAddress((void**)&kl, g_kl);
    cudaGetSymbolAddress((void**)&vh, g_vh);
    cudaGetSymbolAddress((void**)&vl, g_vl);

    cudaFuncSetAttribute(gemm_hmma,
                         cudaFuncAttributeMaxDynamicSharedMemorySize, GEMM_SMEM);
    cudaFuncSetAttribute(attn_tc,
                         cudaFuncAttributeMaxDynamicSharedMemorySize, ATTN_SMEM);

    // 0) rope table + split x / weights into bf16 hi/lo
    rope_table_kernel<<<S_ * 16 / 256, 256>>>();
    {
        const int n4x = M_ROWS * D_ / 4;
        cvt_split<<<n4x / 256, 256>>>((const float4*)x, (uint2*)ahi, (uint2*)alo, n4x);
        const int n4w = QKV_N * D_ / 4;
        cvt_split<<<n4w / 256, 256>>>((const float4*)wqkv_w, (uint2*)whi, (uint2*)wlo, n4w);
        const int n4o = D_ * D_ / 4;
        cvt_split<<<n4o / 256, 256>>>((const float4*)out_w, (uint2*)ohi, (uint2*)olo, n4o);
    }

    // 1) QKV = X @ Wqkv^T + b
    dim3 g1(QKV_N / 128, M_ROWS / 128);
    gemm_hmma<<<g1, 256, GEMM_SMEM>>>(ahi, alo, whi, wlo, wqkv_b, qkv,
                                      M_ROWS, QKV_N, D_);

    // 2) fused RoPE(table) + scale + split qkv -> head-major bf16 hi/lo
    cvt_qkv<<<(M_ROWS * QKV_N / 4) / 256, 256>>>((const float4*)qkv);

    // 3) causal attention -> ctx (written directly as hi/lo into ahi/alo)
    dim3 ga(S_ / 256, H_, B_);
    attn_tc<<<ga, 512, ATTN_SMEM>>>(qh, ql, kh, kl, vh, vl, ahi, alo);

    // 4) out = ctx @ Wout^T + b
    dim3 g2(D_ / 128, M_ROWS / 128);
    gemm_hmma<<<g2, 256, GEMM_SMEM>>>(ahi, alo, ohi, olo, out_b, out,
                                      M_ROWS, D_, D_);
}

// round 14
// speedup vs baseline: 1.5637x; 1.5637x over previous
#include <cuda_runtime.h>
#include <cuda_bf16.h>
#include <cstdint>

// Problem constants
#define B_  2
#define S_  2048
#define D_  2560
#define H_  32
#define HD_ 80
#define RD_ 32

constexpr int M_ROWS = B_ * S_;       // 4096
constexpr int QKV_N  = 3 * D_;        // 7680

// Scratch (no allocation allowed -> __device__ globals)
__device__ float g_qkv[(size_t)M_ROWS * QKV_N];   // fp32 qkv from GEMM1
__device__ float g_rope_tab[S_ * 32];             // [s][0..15]=cos, [16..31]=sin
// bf16 hi/lo split operands for GEMMs
__device__ __align__(256) __nv_bfloat16 g_ahi[(size_t)M_ROWS * D_];   // x / ctx
__device__ __align__(256) __nv_bfloat16 g_alo[(size_t)M_ROWS * D_];
__device__ __align__(256) __nv_bfloat16 g_whi[(size_t)QKV_N  * D_];
__device__ __align__(256) __nv_bfloat16 g_wlo[(size_t)QKV_N  * D_];
__device__ __align__(256) __nv_bfloat16 g_ohi[(size_t)D_ * D_];
__device__ __align__(256) __nv_bfloat16 g_olo[(size_t)D_ * D_];
// head-major pre-split q/k/v: [b][h][s][80]
constexpr size_t HM_SZ = (size_t)B_ * H_ * S_ * HD_;
__device__ __align__(256) __nv_bfloat16 g_qh[HM_SZ], g_ql[HM_SZ];
__device__ __align__(256) __nv_bfloat16 g_kh[HM_SZ], g_kl[HM_SZ];
__device__ __align__(256) __nv_bfloat16 g_vh[HM_SZ], g_vl[HM_SZ];

// ---------------------------------------------------------------------------
// PTX helpers
// ---------------------------------------------------------------------------
__device__ __forceinline__ uint32_t smem_u32(const void* p) {
    uint32_t a;
    asm("{ .reg .u64 t; cvta.to.shared.u64 t, %1; cvt.u32.u64 %0, t; }"
        : "=r"(a) : "l"(p));
    return a;
}
__device__ __forceinline__ void ldsm4u(uint32_t* r, uint32_t addr) {
    asm volatile("ldmatrix.sync.aligned.m8n8.x4.shared.b16 {%0,%1,%2,%3}, [%4];"
                 : "=r"(r[0]), "=r"(r[1]), "=r"(r[2]), "=r"(r[3]) : "r"(addr));
}
__device__ __forceinline__ void ldsm4t(uint32_t* r, uint32_t addr) {
    asm volatile("ldmatrix.sync.aligned.m8n8.x4.trans.shared.b16 {%0,%1,%2,%3}, [%4];"
                 : "=r"(r[0]), "=r"(r[1]), "=r"(r[2]), "=r"(r[3]) : "r"(addr));
}
__device__ __forceinline__ void mma16816(float* c, const uint32_t* a,
                                         uint32_t b0, uint32_t b1)
{
    asm volatile(
        "mma.sync.aligned.m16n8k16.row.col.f32.bf16.bf16.f32 "
        "{%0,%1,%2,%3}, {%4,%5,%6,%7}, {%8,%9}, {%0,%1,%2,%3};"
        : "+f"(c[0]), "+f"(c[1]), "+f"(c[2]), "+f"(c[3])
        : "r"(a[0]), "r"(a[1]), "r"(a[2]), "r"(a[3]), "r"(b0), "r"(b1));
}
__device__ __forceinline__ void cp_async16(uint32_t dst, const void* src) {
    asm volatile("cp.async.cg.shared.global [%0], [%1], 16;"
                 :: "r"(dst), "l"((unsigned long long)__cvta_generic_to_global(src)));
}
#define CP_COMMIT() asm volatile("cp.async.commit_group;" ::: "memory")

#define SWZ64(o) ((o) ^ (((o) >> 3) & 0x30))

__device__ __forceinline__ float ex2f(float x) {
    float r;
    asm("ex2.approx.f32 %0, %1;" : "=f"(r) : "f"(x));
    return r;
}

__device__ __forceinline__ void split2(float x, float y, uint32_t& hi, uint32_t& lo) {
    __nv_bfloat162 h = __floats2bfloat162_rn(x, y);
    float2 f = __bfloat1622float2(h);
    __nv_bfloat162 l = __floats2bfloat162_rn(x - f.x, y - f.y);
    hi = *(uint32_t*)&h;
    lo = *(uint32_t*)&l;
}
__device__ __forceinline__ void split4(float4 v, uint2& hi, uint2& lo) {
    split2(v.x, v.y, hi.x, lo.x);
    split2(v.z, v.w, hi.y, lo.y);
}

// ---------------------------------------------------------------------------
// fp32 -> bf16 hi/lo split (elementwise, same layout)
// ---------------------------------------------------------------------------
__global__ void cvt_split(const float4* __restrict__ in, uint2* __restrict__ hi,
                          uint2* __restrict__ lo, int n4)
{
    int i = blockIdx.x * blockDim.x + threadIdx.x;
    if (i >= n4) return;
    uint2 h, l;
    split4(in[i], h, l);
    hi[i] = h;
    lo[i] = l;
}

// ---------------------------------------------------------------------------
// RoPE cos/sin table (fp64 angle path, bit-matching the reference).
// ---------------------------------------------------------------------------
__global__ void rope_table_kernel()
{
    const int t = blockIdx.x * blockDim.x + threadIdx.x;   // 0..32767
    const int i = t & 15;
    const int s = t >> 4;
    const double inv = exp2(-(double)i * (13.287712379549449 / 16.0));
    const float ang  = (float)((double)s * inv);
    g_rope_tab[s * 32 + i]      = cosf(ang);
    g_rope_tab[s * 32 + 16 + i] = sinf(ang);
}

// ---------------------------------------------------------------------------
// Fused RoPE(table) + split: qkv fp32 -> head-major bf16 hi/lo q/k/v.
// q pre-scaled by (1/sqrt(80)) * log2(e) -> attention softmax in exp2 domain.
// ---------------------------------------------------------------------------
__global__ void cvt_qkv(const float4* __restrict__ qkv4)
{
    int idx = blockIdx.x * blockDim.x + threadIdx.x;
    const int n4 = M_ROWS * QKV_N / 4;
    if (idx >= n4) return;
    const int col4 = idx % (QKV_N / 4);
    const int rowm = idx / (QKV_N / 4);      // b*S + s
    const int col  = col4 * 4;
    const int part = col / D_;
    const int win  = col % D_;
    const int h    = win / HD_;
    const int d    = win % HD_;
    const int b    = rowm >> 11;
    const int s    = rowm & (S_ - 1);

    float4 v = qkv4[idx];

    if (part < 2 && d < RD_) {
        const bool first = (d < 16);
        const int  i     = first ? d : d - 16;
        const float4 cv  = *(const float4*)&g_rope_tab[s * 32 + i];
        const float4 sv  = *(const float4*)&g_rope_tab[s * 32 + 16 + i];
        const float4 ov  = qkv4[idx + (first ? 4 : -4)];
        if (first) {
            v.x = v.x * cv.x - ov.x * sv.x;
            v.y = v.y * cv.y - ov.y * sv.y;
            v.z = v.z * cv.z - ov.z * sv.z;
            v.w = v.w * cv.w - ov.w * sv.w;
        } else {
            v.x = ov.x * sv.x + v.x * cv.x;
            v.y = ov.y * sv.y + v.y * cv.y;
            v.z = ov.z * sv.z + v.z * cv.z;
            v.w = ov.w * sv.w + v.w * cv.w;
        }
    }
    if (part == 0) {   // fold softmax scale AND log2(e) into q
        const float scale = 0.11180339887498949f * 1.4426950408889634f;
        v.x *= scale; v.y *= scale; v.z *= scale; v.w *= scale;
    }

    uint2 hi, lo;
    split4(v, hi, lo);
    const size_t dst = (((size_t)(b * H_ + h)) * S_ + s) * HD_ + d;
    __nv_bfloat16 *ph, *pl;
    if (part == 0)      { ph = g_qh; pl = g_ql; }
    else if (part == 1) { ph = g_kh; pl = g_kl; }
    else                { ph = g_vh; pl = g_vl; }
    *(uint2*)&ph[dst] = hi;
    *(uint2*)&pl[dst] = lo;
}

// ---------------------------------------------------------------------------
// HMMA bf16x3 NT GEMM (verified, unchanged).
// ---------------------------------------------------------------------------
constexpr int GEMM_SMEM = 3 * 32768;

__global__ __launch_bounds__(256, 2)
void gemm_hmma(const __nv_bfloat16* __restrict__ Ahi, const __nv_bfloat16* __restrict__ Alo,
               const __nv_bfloat16* __restrict__ Bhi, const __nv_bfloat16* __restrict__ Blo,
               const float* __restrict__ bias, float* __restrict__ C,
               int M, int N, int K)
{
    extern __shared__ __align__(1024) char gsm[];
    const uint32_t sb = smem_u32(gsm);
    const int tid  = threadIdx.x;
    const int lane = tid & 31;
    const int wid  = tid >> 5;
    const int wm0  = (wid & 3) * 32;
    const int wn0  = (wid >> 2) * 64;
    const int bm   = blockIdx.y * 128;
    const int bn   = blockIdx.x * 128;
    const int lr   = lane & 7;
    const int g    = lane >> 3;

    const __nv_bfloat16* s0 = Ahi + (size_t)bm * K;
    const __nv_bfloat16* s1 = Alo + (size_t)bm * K;
    const __nv_bfloat16* s2 = Bhi + (size_t)bn * K;
    const __nv_bfloat16* s3 = Blo + (size_t)bn * K;

    float acc[2][8][4] = {};

    auto load_stage = [&](int s) {
        const uint32_t st = sb + (uint32_t)(s % 3) * 32768;
        #pragma unroll
        for (int it = 0; it < 8; ++it) {
            const int tile = it >> 1;
            const int idx  = tid + (it & 1) * 256;
            const int row  = idx >> 2;
            const int c    = idx & 3;
            const __nv_bfloat16* base =
                (tile == 0) ? s0 : (tile == 1) ? s1 : (tile == 2) ? s2 : s3;
            const __nv_bfloat16* gp = base + (size_t)row * K + s * 32 + c * 8;
            cp_async16(st + tile * 8192 + SWZ64((uint32_t)(row * 64 + c * 16)), gp);
        }
        CP_COMMIT();
    };

    const int nst = K >> 5;
    load_stage(0);
    load_stage(1);

    for (int s = 0; s < nst; ++s) {
        if (s + 1 < nst)
            asm volatile("cp.async.wait_group 1;" ::: "memory");
        else
            asm volatile("cp.async.wait_group 0;" ::: "memory");
        __syncthreads();
        if (s + 2 < nst) load_stage(s + 2);

        const uint32_t st = sb + (uint32_t)(s % 3) * 32768;
        #pragma unroll
        for (int ks = 0; ks < 2; ++ks) {
            uint32_t ah[2][4], al[2][4];
            #pragma unroll
            for (int mi = 0; mi < 2; ++mi) {
                const uint32_t ro = (uint32_t)((wm0 + mi * 16 + lr + (g & 1) * 8) * 64
                                               + ks * 32 + (g >> 1) * 16);
                ldsm4u(ah[mi], st + SWZ64(ro));
                ldsm4u(al[mi], st + 8192 + SWZ64(ro));
            }
            #pragma unroll
            for (int np = 0; np < 4; ++np) {
                const uint32_t ro = (uint32_t)((wn0 + np * 16 + lr + (g >> 1) * 8) * 64
                                               + ks * 32 + (g & 1) * 16);
                uint32_t bh[4], bl[4];
                ldsm4u(bh, st + 16384 + SWZ64(ro));
                ldsm4u(bl, st + 24576 + SWZ64(ro));
                #pragma unroll
                for (int half = 0; half < 2; ++half) {
                    const int ni = np * 2 + half;
                    #pragma unroll
                    for (int mi = 0; mi < 2; ++mi) {
                        mma16816(acc[mi][ni], ah[mi], bh[half * 2], bh[half * 2 + 1]);
                        mma16816(acc[mi][ni], ah[mi], bl[half * 2], bl[half * 2 + 1]);
                        mma16816(acc[mi][ni], al[mi], bh[half * 2], bh[half * 2 + 1]);
                    }
                }
            }
        }
    }

    #pragma unroll
    for (int ni = 0; ni < 8; ++ni) {
        const int col = bn + wn0 + ni * 8 + (lane & 3) * 2;
        const float2 bv = *(const float2*)&bias[col];
        #pragma unroll
        for (int mi = 0; mi < 2; ++mi) {
            const int row = bm + wm0 + mi * 16 + (lane >> 2);
            *(float2*)&C[(size_t)row * N + col] =
                make_float2(acc[mi][ni][0] + bv.x, acc[mi][ni][1] + bv.y);
            *(float2*)&C[(size_t)(row + 8) * N + col] =
                make_float2(acc[mi][ni][2] + bv.x, acc[mi][ni][3] + bv.y);
        }
    }
}

// ---------------------------------------------------------------------------
// Causal flash attention, HMMA bf16x3, x4-ldmatrix loads (round-11 champion
// structure); softmax in exp2 domain (log2e folded into q upstream).
// ---------------------------------------------------------------------------
constexpr int ATTN_SMEM = 2 * 45056;   // 90112

__global__ __launch_bounds__(256, 1)
void attn_tc(const __nv_bfloat16* __restrict__ qh_g, const __nv_bfloat16* __restrict__ ql_g,
             const __nv_bfloat16* __restrict__ kh_g, const __nv_bfloat16* __restrict__ kl_g,
             const __nv_bfloat16* __restrict__ vh_g, const __nv_bfloat16* __restrict__ vl_g,
             __nv_bfloat16* __restrict__ chi, __nv_bfloat16* __restrict__ clo)
{
    extern __shared__ __align__(1024) char smc[];
    const uint32_t sb = smem_u32(smc);
    const int qt   = gridDim.x - 1 - blockIdx.x;   // big tiles first
    const int h    = blockIdx.y;
    const int b    = blockIdx.z;
    const int tid  = threadIdx.x;
    const int lane = tid & 31;
    const int wid  = tid >> 5;
    const int wm   = wid * 16;
    const int lr   = lane & 7;
    const int g    = lane >> 3;

    const size_t hb = ((size_t)(b * H_ + h)) * S_ * HD_;

    // ---- stage Q (hi at 0, lo at 22528) and load fragments ----
    for (int t = tid; t < 2560; t += 256) {
        const int arr = t / 1280, rem = t % 1280;
        const int row = rem / 10, c = rem % 10;
        const __nv_bfloat16* src = (arr ? ql_g : qh_g) + hb
                                   + (size_t)(qt * 128 + row) * HD_ + c * 8;
        cp_async16(sb + (uint32_t)(arr * 22528 + row * 176 + c * 16), src);
    }
    CP_COMMIT();
    asm volatile("cp.async.wait_group 0;" ::: "memory");
    __syncthreads();

    uint32_t qh[5][4], ql[5][4];
    #pragma unroll
    for (int ks = 0; ks < 5; ++ks) {
        const uint32_t ro = (uint32_t)((wm + lr + (g & 1) * 8) * 176 + ks * 32 + (g >> 1) * 16);
        ldsm4u(qh[ks], sb + ro);
        ldsm4u(ql[ks], sb + 22528 + ro);
    }
    __syncthreads();

    auto load_kv = [&](int kt) {
        const uint32_t st = sb + (uint32_t)(kt & 1) * 45056;
        const __nv_bfloat16* srcs[4] = { kh_g, kl_g, vh_g, vl_g };
        #pragma unroll
        for (int it = 0; it < 10; ++it) {
            const int t = tid + it * 256;
            const int arr = t / 640, rem = t % 640;
            const int row = rem / 10, c = rem % 10;
            const __nv_bfloat16* src = srcs[arr] + hb
                                       + (size_t)(kt * 64 + row) * HD_ + c * 8;
            cp_async16(st + (uint32_t)(arr * 11264 + row * 176 + c * 16), src);
        }
        CP_COMMIT();
    };

    float o[10][4] = {};
    float mx0 = -1e30f, mx1 = -1e30f, l0 = 0.f, l1 = 0.f;
    const int nkt = 2 * qt + 2;

    load_kv(0);

    // x4 ldmatrix lane-address components (conflict-free)
    const uint32_t krow = (uint32_t)(((lane >> 4) * 8 + lr) * 176 + ((lane >> 3) & 1) * 16);
    const uint32_t vrow = (uint32_t)((((lane >> 3) & 1) * 8 + lr) * 176 + (lane >> 4) * 16);

    for (int kt = 0; kt < nkt; ++kt) {
        if (kt + 1 < nkt) {
            load_kv(kt + 1);
            asm volatile("cp.async.wait_group 1;" ::: "memory");
        } else {
            asm volatile("cp.async.wait_group 0;" ::: "memory");
        }
        __syncthreads();

        const bool active = (qt * 128 + wm + 15 >= kt * 64);
        if (active) {
            const uint32_t st = sb + (uint32_t)(kt & 1) * 45056;

            // ---- scores S = Q K^T (bf16x3), 16 keys per ldsm.x4 ----
            float s[8][4];
            #pragma unroll
            for (int nb2 = 0; nb2 < 4; ++nb2) {
                float* sA = s[nb2 * 2];
                float* sB = s[nb2 * 2 + 1];
                sA[0] = sA[1] = sA[2] = sA[3] = 0.f;
                sB[0] = sB[1] = sB[2] = sB[3] = 0.f;
                const uint32_t rbase = st + (uint32_t)(nb2 * 16 * 176) + krow;
                #pragma unroll
                for (int ks = 0; ks < 5; ++ks) {
                    uint32_t kh4[4], kl4[4];
                    const uint32_t ro = rbase + ks * 32;
                    ldsm4u(kh4, ro);
                    ldsm4u(kl4, ro + 11264);
                    mma16816(sA, qh[ks], kh4[0], kh4[1]);
                    mma16816(sA, qh[ks], kl4[0], kl4[1]);
                    mma16816(sA, ql[ks], kh4[0], kh4[1]);
                    mma16816(sB, qh[ks], kh4[2], kh4[3]);
                    mma16816(sB, qh[ks], kl4[2], kl4[3]);
                    mma16816(sB, ql[ks], kh4[2], kh4[3]);
                }
            }
            if (kt >= 2 * qt) {   // diagonal-region mask
                const int r0 = qt * 128 + wm + (lane >> 2);
                #pragma unroll
                for (int nb = 0; nb < 8; ++nb) {
                    const int c0 = kt * 64 + nb * 8 + (lane & 3) * 2;
                    if (c0     > r0)     s[nb][0] = -1e30f;
                    if (c0 + 1 > r0)     s[nb][1] = -1e30f;
                    if (c0     > r0 + 8) s[nb][2] = -1e30f;
                    if (c0 + 1 > r0 + 8) s[nb][3] = -1e30f;
                }
            }

            // ---- online softmax (exp2 domain) ----
            float m0 = -1e30f, m1 = -1e30f;
            #pragma unroll
            for (int nb = 0; nb < 8; ++nb) {
                m0 = fmaxf(m0, fmaxf(s[nb][0], s[nb][1]));
                m1 = fmaxf(m1, fmaxf(s[nb][2], s[nb][3]));
            }
            m0 = fmaxf(m0, __shfl_xor_sync(0xffffffffu, m0, 1));
            m0 = fmaxf(m0, __shfl_xor_sync(0xffffffffu, m0, 2));
            m1 = fmaxf(m1, __shfl_xor_sync(0xffffffffu, m1, 1));
            m1 = fmaxf(m1, __shfl_xor_sync(0xffffffffu, m1, 2));
            const float mn0 = fmaxf(mx0, m0), mn1 = fmaxf(mx1, m1);
            const float corr0 = ex2f(mx0 - mn0), corr1 = ex2f(mx1 - mn1);
            mx0 = mn0; mx1 = mn1;
            float sum0 = 0.f, sum1 = 0.f;
            #pragma unroll
            for (int nb = 0; nb < 8; ++nb) {
                s[nb][0] = ex2f(s[nb][0] - mn0);
                s[nb][1] = ex2f(s[nb][1] - mn0);
                s[nb][2] = ex2f(s[nb][2] - mn1);
                s[nb][3] = ex2f(s[nb][3] - mn1);
                sum0 += s[nb][0] + s[nb][1];
                sum1 += s[nb][2] + s[nb][3];
            }
            sum0 += __shfl_xor_sync(0xffffffffu, sum0, 1);
            sum0 += __shfl_xor_sync(0xffffffffu, sum0, 2);
            sum1 += __shfl_xor_sync(0xffffffffu, sum1, 1);
            sum1 += __shfl_xor_sync(0xffffffffu, sum1, 2);
            l0 = l0 * corr0 + sum0;
            l1 = l1 * corr1 + sum1;
            #pragma unroll
            for (int nd = 0; nd < 10; ++nd) {
                o[nd][0] *= corr0; o[nd][1] *= corr0;
                o[nd][2] *= corr1; o[nd][3] *= corr1;
            }

            // ---- P -> bf16 hi/lo fragments ----
            uint32_t ph[4][4], pl[4][4];
            #pragma unroll
            for (int kb = 0; kb < 4; ++kb) {
                split2(s[2 * kb][0],     s[2 * kb][1],     ph[kb][0], pl[kb][0]);
                split2(s[2 * kb][2],     s[2 * kb][3],     ph[kb][1], pl[kb][1]);
                split2(s[2 * kb + 1][0], s[2 * kb + 1][1], ph[kb][2], pl[kb][2]);
                split2(s[2 * kb + 1][2], s[2 * kb + 1][3], ph[kb][3], pl[kb][3]);
            }

            // ---- O += P V (bf16x3), two nd blocks per ldsm.x4.trans ----
            #pragma unroll
            for (int nd2 = 0; nd2 < 5; ++nd2) {
                float* oA = o[nd2 * 2];
                float* oB = o[nd2 * 2 + 1];
                const uint32_t cbase = st + 22528 + (uint32_t)(nd2 * 32) + vrow;
                #pragma unroll
                for (int kb = 0; kb < 4; ++kb) {
                    uint32_t vh4[4], vl4[4];
                    const uint32_t ro = cbase + (uint32_t)(kb * 16 * 176);
                    ldsm4t(vh4, ro);
                    ldsm4t(vl4, ro + 11264);
                    mma16816(oA, ph[kb], vh4[0], vh4[1]);
                    mma16816(oA, ph[kb], vl4[0], vl4[1]);
                    mma16816(oA, pl[kb], vh4[0], vh4[1]);
                    mma16816(oB, ph[kb], vh4[2], vh4[3]);
                    mma16816(oB, ph[kb], vl4[2], vl4[3]);
                    mma16816(oB, pl[kb], vh4[2], vh4[3]);
                }
            }
        }
        __syncthreads();
    }

    const float inv0 = 1.f / l0, inv1 = 1.f / l1;
    const int r0 = qt * 128 + wm + (lane >> 2);
    #pragma unroll
    for (int nd = 0; nd < 10; ++nd) {
        const int col = h * HD_ + nd * 8 + (lane & 3) * 2;
        uint32_t hi, lo;
        split2(o[nd][0] * inv0, o[nd][1] * inv0, hi, lo);
        *(uint32_t*)&chi[((size_t)(b * S_ + r0)) * D_ + col] = hi;
        *(uint32_t*)&clo[((size_t)(b * S_ + r0)) * D_ + col] = lo;
        split2(o[nd][2] * inv1, o[nd][3] * inv1, hi, lo);
        *(uint32_t*)&chi[((size_t)(b * S_ + r0 + 8)) * D_ + col] = hi;
        *(uint32_t*)&clo[((size_t)(b * S_ + r0 + 8)) * D_ + col] = lo;
    }
}

// ---------------------------------------------------------------------------
// Launch
// ---------------------------------------------------------------------------
extern "C" void kernel_launch(void* const* d_in, const int* in_sizes, int n_in,
                              void* d_out, int out_size)
{
    const float* x      = (const float*)d_in[0];
    const float* wqkv_w = (const float*)d_in[1];
    const float* wqkv_b = (const float*)d_in[2];
    const float* out_w  = (const float*)d_in[3];
    const float* out_b  = (const float*)d_in[4];
    float* out = (float*)d_out;

    float* qkv;
    __nv_bfloat16 *ahi, *alo, *whi, *wlo, *ohi, *olo;
    __nv_bfloat16 *qh, *ql, *kh, *kl, *vh, *vl;
    cudaGetSymbolAddress((void**)&qkv, g_qkv);
    cudaGetSymbolAddress((void**)&ahi, g_ahi);
    cudaGetSymbolAddress((void**)&alo, g_alo);
    cudaGetSymbolAddress((void**)&whi, g_whi);
    cudaGetSymbolAddress((void**)&wlo, g_wlo);
    cudaGetSymbolAddress((void**)&ohi, g_ohi);
    cudaGetSymbolAddress((void**)&olo, g_olo);
    cudaGetSymbolAddress((void**)&qh, g_qh);
    cudaGetSymbolAddress((void**)&ql, g_ql);
    cudaGetSymbolAddress((void**)&kh, g_kh);
    cudaGetSymbolAddress((void**)&kl, g_kl);
    cudaGetSymbolAddress((void**)&vh, g_vh);
    cudaGetSymbolAddress((void**)&vl, g_vl);

    cudaFuncSetAttribute(gemm_hmma,
                         cudaFuncAttributeMaxDynamicSharedMemorySize, GEMM_SMEM);
    cudaFuncSetAttribute(attn_tc,
                         cudaFuncAttributeMaxDynamicSharedMemorySize, ATTN_SMEM);

    // 0) rope table + split x / weights into bf16 hi/lo
    rope_table_kernel<<<S_ * 16 / 256, 256>>>();
    {
        const int n4x = M_ROWS * D_ / 4;
        cvt_split<<<n4x / 256, 256>>>((const float4*)x, (uint2*)ahi, (uint2*)alo, n4x);
        const int n4w = QKV_N * D_ / 4;
        cvt_split<<<n4w / 256, 256>>>((const float4*)wqkv_w, (uint2*)whi, (uint2*)wlo, n4w);
        const int n4o = D_ * D_ / 4;
        cvt_split<<<n4o / 256, 256>>>((const float4*)out_w, (uint2*)ohi, (uint2*)olo, n4o);
    }

    // 1) QKV = X @ Wqkv^T + b
    dim3 g1(QKV_N / 128, M_ROWS / 128);
    gemm_hmma<<<g1, 256, GEMM_SMEM>>>(ahi, alo, whi, wlo, wqkv_b, qkv,
                                      M_ROWS, QKV_N, D_);

    // 2) fused RoPE(table) + scale + split qkv -> head-major bf16 hi/lo
    cvt_qkv<<<(M_ROWS * QKV_N / 4) / 256, 256>>>((const float4*)qkv);

    // 3) causal attention -> ctx (written directly as hi/lo into ahi/alo)
    dim3 ga(S_ / 128, H_, B_);
    attn_tc<<<ga, 256, ATTN_SMEM>>>(qh, ql, kh, kl, vh, vl, ahi, alo);

    // 4) out = ctx @ Wout^T + b
    dim3 g2(D_ / 128, M_ROWS / 128);
    gemm_hmma<<<g2, 256, GEMM_SMEM>>>(ahi, alo, ohi, olo, out_b, out,
                                      M_ROWS, D_, D_);
}

// round 15
// speedup vs baseline: 1.7657x; 1.1291x over previous
#include <cuda_runtime.h>
#include <cuda_bf16.h>
#include <cuda_fp16.h>
#include <cstdint>

// Problem constants
#define B_  2
#define S_  2048
#define D_  2560
#define H_  32
#define HD_ 80
#define RD_ 32

constexpr int M_ROWS = B_ * S_;       // 4096
constexpr int QKV_N  = 3 * D_;        // 7680

// Scratch (no allocation allowed -> __device__ globals)
__device__ float g_qkv[(size_t)M_ROWS * QKV_N];   // fp32 qkv from GEMM1
__device__ float g_rope_tab[S_ * 32];             // [s][0..15]=cos, [16..31]=sin
// bf16 hi/lo split operands for GEMMs
__device__ __align__(256) __nv_bfloat16 g_ahi[(size_t)M_ROWS * D_];   // x / ctx
__device__ __align__(256) __nv_bfloat16 g_alo[(size_t)M_ROWS * D_];
__device__ __align__(256) __nv_bfloat16 g_whi[(size_t)QKV_N  * D_];
__device__ __align__(256) __nv_bfloat16 g_wlo[(size_t)QKV_N  * D_];
__device__ __align__(256) __nv_bfloat16 g_ohi[(size_t)D_ * D_];
__device__ __align__(256) __nv_bfloat16 g_olo[(size_t)D_ * D_];
// head-major fp16 q/k/v: [b][h][s][80]
constexpr size_t HM_SZ = (size_t)B_ * H_ * S_ * HD_;
__device__ __align__(256) __half g_qf[HM_SZ];
__device__ __align__(256) __half g_kf[HM_SZ];
__device__ __align__(256) __half g_vf[HM_SZ];

// ---------------------------------------------------------------------------
// PTX helpers
// ---------------------------------------------------------------------------
__device__ __forceinline__ uint32_t smem_u32(const void* p) {
    uint32_t a;
    asm("{ .reg .u64 t; cvta.to.shared.u64 t, %1; cvt.u32.u64 %0, t; }"
        : "=r"(a) : "l"(p));
    return a;
}
__device__ __forceinline__ void ldsm4u(uint32_t* r, uint32_t addr) {
    asm volatile("ldmatrix.sync.aligned.m8n8.x4.shared.b16 {%0,%1,%2,%3}, [%4];"
                 : "=r"(r[0]), "=r"(r[1]), "=r"(r[2]), "=r"(r[3]) : "r"(addr));
}
__device__ __forceinline__ void ldsm4t(uint32_t* r, uint32_t addr) {
    asm volatile("ldmatrix.sync.aligned.m8n8.x4.trans.shared.b16 {%0,%1,%2,%3}, [%4];"
                 : "=r"(r[0]), "=r"(r[1]), "=r"(r[2]), "=r"(r[3]) : "r"(addr));
}
// bf16 HMMA (GEMMs)
__device__ __forceinline__ void mma16816(float* c, const uint32_t* a,
                                         uint32_t b0, uint32_t b1)
{
    asm volatile(
        "mma.sync.aligned.m16n8k16.row.col.f32.bf16.bf16.f32 "
        "{%0,%1,%2,%3}, {%4,%5,%6,%7}, {%8,%9}, {%0,%1,%2,%3};"
        : "+f"(c[0]), "+f"(c[1]), "+f"(c[2]), "+f"(c[3])
        : "r"(a[0]), "r"(a[1]), "r"(a[2]), "r"(a[3]), "r"(b0), "r"(b1));
}
// fp16 HMMA (attention)
__device__ __forceinline__ void mma16816h(float* c, const uint32_t* a,
                                          uint32_t b0, uint32_t b1)
{
    asm volatile(
        "mma.sync.aligned.m16n8k16.row.col.f32.f16.f16.f32 "
        "{%0,%1,%2,%3}, {%4,%5,%6,%7}, {%8,%9}, {%0,%1,%2,%3};"
        : "+f"(c[0]), "+f"(c[1]), "+f"(c[2]), "+f"(c[3])
        : "r"(a[0]), "r"(a[1]), "r"(a[2]), "r"(a[3]), "r"(b0), "r"(b1));
}
__device__ __forceinline__ void cp_async16(uint32_t dst, const void* src) {
    asm volatile("cp.async.cg.shared.global [%0], [%1], 16;"
                 :: "r"(dst), "l"((unsigned long long)__cvta_generic_to_global(src)));
}
#define CP_COMMIT() asm volatile("cp.async.commit_group;" ::: "memory")

#define SWZ64(o) ((o) ^ (((o) >> 3) & 0x30))

__device__ __forceinline__ float ex2f(float x) {
    float r;
    asm("ex2.approx.f32 %0, %1;" : "=f"(r) : "f"(x));
    return r;
}

__device__ __forceinline__ void split2(float x, float y, uint32_t& hi, uint32_t& lo) {
    __nv_bfloat162 h = __floats2bfloat162_rn(x, y);
    float2 f = __bfloat1622float2(h);
    __nv_bfloat162 l = __floats2bfloat162_rn(x - f.x, y - f.y);
    hi = *(uint32_t*)&h;
    lo = *(uint32_t*)&l;
}
__device__ __forceinline__ void split4(float4 v, uint2& hi, uint2& lo) {
    split2(v.x, v.y, hi.x, lo.x);
    split2(v.z, v.w, hi.y, lo.y);
}
__device__ __forceinline__ uint32_t h2pack(float x, float y) {
    __half2 h = __floats2half2_rn(x, y);
    return *(uint32_t*)&h;
}

// ---------------------------------------------------------------------------
// fp32 -> bf16 hi/lo split (elementwise; GEMM operands)
// ---------------------------------------------------------------------------
__global__ void cvt_split(const float4* __restrict__ in, uint2* __restrict__ hi,
                          uint2* __restrict__ lo, int n4)
{
    int i = blockIdx.x * blockDim.x + threadIdx.x;
    if (i >= n4) return;
    uint2 h, l;
    split4(in[i], h, l);
    hi[i] = h;
    lo[i] = l;
}

// ---------------------------------------------------------------------------
// RoPE cos/sin table (fp64 angle path, bit-matching the reference).
// ---------------------------------------------------------------------------
__global__ void rope_table_kernel()
{
    const int t = blockIdx.x * blockDim.x + threadIdx.x;   // 0..32767
    const int i = t & 15;
    const int s = t >> 4;
    const double inv = exp2(-(double)i * (13.287712379549449 / 16.0));
    const float ang  = (float)((double)s * inv);
    g_rope_tab[s * 32 + i]      = cosf(ang);
    g_rope_tab[s * 32 + 16 + i] = sinf(ang);
}

// ---------------------------------------------------------------------------
// Fused RoPE(table) + convert: qkv fp32 -> head-major fp16 q/k/v.
// q pre-scaled by (1/sqrt(80)) * log2(e) -> attention softmax in exp2 domain.
// ---------------------------------------------------------------------------
__global__ void cvt_qkv(const float4* __restrict__ qkv4)
{
    int idx = blockIdx.x * blockDim.x + threadIdx.x;
    const int n4 = M_ROWS * QKV_N / 4;
    if (idx >= n4) return;
    const int col4 = idx % (QKV_N / 4);
    const int rowm = idx / (QKV_N / 4);      // b*S + s
    const int col  = col4 * 4;
    const int part = col / D_;
    const int win  = col % D_;
    const int h    = win / HD_;
    const int d    = win % HD_;
    const int b    = rowm >> 11;
    const int s    = rowm & (S_ - 1);

    float4 v = qkv4[idx];

    if (part < 2 && d < RD_) {
        const bool first = (d < 16);
        const int  i     = first ? d : d - 16;
        const float4 cv  = *(const float4*)&g_rope_tab[s * 32 + i];
        const float4 sv  = *(const float4*)&g_rope_tab[s * 32 + 16 + i];
        const float4 ov  = qkv4[idx + (first ? 4 : -4)];
        if (first) {
            v.x = v.x * cv.x - ov.x * sv.x;
            v.y = v.y * cv.y - ov.y * sv.y;
            v.z = v.z * cv.z - ov.z * sv.z;
            v.w = v.w * cv.w - ov.w * sv.w;
        } else {
            v.x = ov.x * sv.x + v.x * cv.x;
            v.y = ov.y * sv.y + v.y * cv.y;
            v.z = ov.z * sv.z + v.z * cv.z;
            v.w = ov.w * sv.w + v.w * cv.w;
        }
    }
    if (part == 0) {   // fold softmax scale AND log2(e) into q
        const float scale = 0.11180339887498949f * 1.4426950408889634f;
        v.x *= scale; v.y *= scale; v.z *= scale; v.w *= scale;
    }

    uint2 hp;
    hp.x = h2pack(v.x, v.y);
    hp.y = h2pack(v.z, v.w);
    const size_t dst = (((size_t)(b * H_ + h)) * S_ + s) * HD_ + d;
    __half* pf = (part == 0) ? g_qf : (part == 1) ? g_kf : g_vf;
    *(uint2*)&pf[dst] = hp;
}

// ---------------------------------------------------------------------------
// HMMA bf16x3 NT GEMM (verified, unchanged).
// ---------------------------------------------------------------------------
constexpr int GEMM_SMEM = 3 * 32768;

__global__ __launch_bounds__(256, 2)
void gemm_hmma(const __nv_bfloat16* __restrict__ Ahi, const __nv_bfloat16* __restrict__ Alo,
               const __nv_bfloat16* __restrict__ Bhi, const __nv_bfloat16* __restrict__ Blo,
               const float* __restrict__ bias, float* __restrict__ C,
               int M, int N, int K)
{
    extern __shared__ __align__(1024) char gsm[];
    const uint32_t sb = smem_u32(gsm);
    const int tid  = threadIdx.x;
    const int lane = tid & 31;
    const int wid  = tid >> 5;
    const int wm0  = (wid & 3) * 32;
    const int wn0  = (wid >> 2) * 64;
    const int bm   = blockIdx.y * 128;
    const int bn   = blockIdx.x * 128;
    const int lr   = lane & 7;
    const int g    = lane >> 3;

    const __nv_bfloat16* s0 = Ahi + (size_t)bm * K;
    const __nv_bfloat16* s1 = Alo + (size_t)bm * K;
    const __nv_bfloat16* s2 = Bhi + (size_t)bn * K;
    const __nv_bfloat16* s3 = Blo + (size_t)bn * K;

    float acc[2][8][4] = {};

    auto load_stage = [&](int s) {
        const uint32_t st = sb + (uint32_t)(s % 3) * 32768;
        #pragma unroll
        for (int it = 0; it < 8; ++it) {
            const int tile = it >> 1;
            const int idx  = tid + (it & 1) * 256;
            const int row  = idx >> 2;
            const int c    = idx & 3;
            const __nv_bfloat16* base =
                (tile == 0) ? s0 : (tile == 1) ? s1 : (tile == 2) ? s2 : s3;
            const __nv_bfloat16* gp = base + (size_t)row * K + s * 32 + c * 8;
            cp_async16(st + tile * 8192 + SWZ64((uint32_t)(row * 64 + c * 16)), gp);
        }
        CP_COMMIT();
    };

    const int nst = K >> 5;
    load_stage(0);
    load_stage(1);

    for (int s = 0; s < nst; ++s) {
        if (s + 1 < nst)
            asm volatile("cp.async.wait_group 1;" ::: "memory");
        else
            asm volatile("cp.async.wait_group 0;" ::: "memory");
        __syncthreads();
        if (s + 2 < nst) load_stage(s + 2);

        const uint32_t st = sb + (uint32_t)(s % 3) * 32768;
        #pragma unroll
        for (int ks = 0; ks < 2; ++ks) {
            uint32_t ah[2][4], al[2][4];
            #pragma unroll
            for (int mi = 0; mi < 2; ++mi) {
                const uint32_t ro = (uint32_t)((wm0 + mi * 16 + lr + (g & 1) * 8) * 64
                                               + ks * 32 + (g >> 1) * 16);
                ldsm4u(ah[mi], st + SWZ64(ro));
                ldsm4u(al[mi], st + 8192 + SWZ64(ro));
            }
            #pragma unroll
            for (int np = 0; np < 4; ++np) {
                const uint32_t ro = (uint32_t)((wn0 + np * 16 + lr + (g >> 1) * 8) * 64
                                               + ks * 32 + (g & 1) * 16);
                uint32_t bh[4], bl[4];
                ldsm4u(bh, st + 16384 + SWZ64(ro));
                ldsm4u(bl, st + 24576 + SWZ64(ro));
                #pragma unroll
                for (int half = 0; half < 2; ++half) {
                    const int ni = np * 2 + half;
                    #pragma unroll
                    for (int mi = 0; mi < 2; ++mi) {
                        mma16816(acc[mi][ni], ah[mi], bh[half * 2], bh[half * 2 + 1]);
                        mma16816(acc[mi][ni], ah[mi], bl[half * 2], bl[half * 2 + 1]);
                        mma16816(acc[mi][ni], al[mi], bh[half * 2], bh[half * 2 + 1]);
                    }
                }
            }
        }
    }

    #pragma unroll
    for (int ni = 0; ni < 8; ++ni) {
        const int col = bn + wn0 + ni * 8 + (lane & 3) * 2;
        const float2 bv = *(const float2*)&bias[col];
        #pragma unroll
        for (int mi = 0; mi < 2; ++mi) {
            const int row = bm + wm0 + mi * 16 + (lane >> 2);
            *(float2*)&C[(size_t)row * N + col] =
                make_float2(acc[mi][ni][0] + bv.x, acc[mi][ni][1] + bv.y);
            *(float2*)&C[(size_t)(row + 8) * N + col] =
                make_float2(acc[mi][ni][2] + bv.x, acc[mi][ni][3] + bv.y);
        }
    }
}

// ---------------------------------------------------------------------------
// Causal flash attention, fp16 single-pass HMMA (round-11 structure).
// smem: Q 22528 | KV buf0 (K 11264 + V 11264) | KV buf1 = 67584 B.
// ---------------------------------------------------------------------------
constexpr int ATTN_SMEM = 22528 + 2 * 22528;   // 67584

__global__ __launch_bounds__(256, 1)
void attn_tc(const __half* __restrict__ qf_g, const __half* __restrict__ kf_g,
             const __half* __restrict__ vf_g,
             __nv_bfloat16* __restrict__ chi, __nv_bfloat16* __restrict__ clo)
{
    extern __shared__ __align__(1024) char smc[];
    const uint32_t sb = smem_u32(smc);
    const int qt   = gridDim.x - 1 - blockIdx.x;   // big tiles first
    const int h    = blockIdx.y;
    const int b    = blockIdx.z;
    const int tid  = threadIdx.x;
    const int lane = tid & 31;
    const int wid  = tid >> 5;
    const int wm   = wid * 16;
    const int lr   = lane & 7;
    const int g    = lane >> 3;

    const size_t hb = ((size_t)(b * H_ + h)) * S_ * HD_;

    // ---- stage Q (fp16, 128 rows x 176B) and load fragments ----
    for (int t = tid; t < 1280; t += 256) {
        const int row = t / 10, c = t % 10;
        cp_async16(sb + (uint32_t)(row * 176 + c * 16),
                   qf_g + hb + (size_t)(qt * 128 + row) * HD_ + c * 8);
    }
    CP_COMMIT();
    asm volatile("cp.async.wait_group 0;" ::: "memory");
    __syncthreads();

    uint32_t qf[5][4];
    #pragma unroll
    for (int ks = 0; ks < 5; ++ks) {
        const uint32_t ro = (uint32_t)((wm + lr + (g & 1) * 8) * 176 + ks * 32 + (g >> 1) * 16);
        ldsm4u(qf[ks], sb + ro);
    }
    __syncthreads();

    const uint32_t KVB = sb + 22528;
    auto load_kv = [&](int kt) {
        const uint32_t st = KVB + (uint32_t)(kt & 1) * 22528;
        #pragma unroll
        for (int it = 0; it < 5; ++it) {
            const int t = tid + it * 256;            // 0..1279
            const int arr = t / 640, rem = t % 640;
            const int row = rem / 10, c = rem % 10;
            const __half* src = (arr ? vf_g : kf_g) + hb
                                + (size_t)(kt * 64 + row) * HD_ + c * 8;
            cp_async16(st + (uint32_t)(arr * 11264 + row * 176 + c * 16), src);
        }
        CP_COMMIT();
    };

    float o[10][4] = {};
    float mx0 = -1e30f, mx1 = -1e30f, l0 = 0.f, l1 = 0.f;
    const int nkt = 2 * qt + 2;

    load_kv(0);

    // x4 ldmatrix lane-address components (conflict-free)
    const uint32_t krow = (uint32_t)(((lane >> 4) * 8 + lr) * 176 + ((lane >> 3) & 1) * 16);
    const uint32_t vrow = (uint32_t)((((lane >> 3) & 1) * 8 + lr) * 176 + (lane >> 4) * 16);

    for (int kt = 0; kt < nkt; ++kt) {
        if (kt + 1 < nkt) {
            load_kv(kt + 1);
            asm volatile("cp.async.wait_group 1;" ::: "memory");
        } else {
            asm volatile("cp.async.wait_group 0;" ::: "memory");
        }
        __syncthreads();

        const bool active = (qt * 128 + wm + 15 >= kt * 64);
        if (active) {
            const uint32_t st = KVB + (uint32_t)(kt & 1) * 22528;

            // ---- scores S = Q K^T (fp16 single pass) ----
            float s[8][4];
            #pragma unroll
            for (int nb2 = 0; nb2 < 4; ++nb2) {
                float* sA = s[nb2 * 2];
                float* sB = s[nb2 * 2 + 1];
                sA[0] = sA[1] = sA[2] = sA[3] = 0.f;
                sB[0] = sB[1] = sB[2] = sB[3] = 0.f;
                const uint32_t rbase = st + (uint32_t)(nb2 * 16 * 176) + krow;
                #pragma unroll
                for (int ks = 0; ks < 5; ++ks) {
                    uint32_t k4[4];
                    ldsm4u(k4, rbase + ks * 32);
                    mma16816h(sA, qf[ks], k4[0], k4[1]);
                    mma16816h(sB, qf[ks], k4[2], k4[3]);
                }
            }
            if (kt >= 2 * qt) {   // diagonal-region mask
                const int r0 = qt * 128 + wm + (lane >> 2);
                #pragma unroll
                for (int nb = 0; nb < 8; ++nb) {
                    const int c0 = kt * 64 + nb * 8 + (lane & 3) * 2;
                    if (c0     > r0)     s[nb][0] = -1e30f;
                    if (c0 + 1 > r0)     s[nb][1] = -1e30f;
                    if (c0     > r0 + 8) s[nb][2] = -1e30f;
                    if (c0 + 1 > r0 + 8) s[nb][3] = -1e30f;
                }
            }

            // ---- online softmax (exp2 domain) ----
            float m0 = -1e30f, m1 = -1e30f;
            #pragma unroll
            for (int nb = 0; nb < 8; ++nb) {
                m0 = fmaxf(m0, fmaxf(s[nb][0], s[nb][1]));
                m1 = fmaxf(m1, fmaxf(s[nb][2], s[nb][3]));
            }
            m0 = fmaxf(m0, __shfl_xor_sync(0xffffffffu, m0, 1));
            m0 = fmaxf(m0, __shfl_xor_sync(0xffffffffu, m0, 2));
            m1 = fmaxf(m1, __shfl_xor_sync(0xffffffffu, m1, 1));
            m1 = fmaxf(m1, __shfl_xor_sync(0xffffffffu, m1, 2));
            const float mn0 = fmaxf(mx0, m0), mn1 = fmaxf(mx1, m1);
            const float corr0 = ex2f(mx0 - mn0), corr1 = ex2f(mx1 - mn1);
            mx0 = mn0; mx1 = mn1;
            float sum0 = 0.f, sum1 = 0.f;
            #pragma unroll
            for (int nb = 0; nb < 8; ++nb) {
                s[nb][0] = ex2f(s[nb][0] - mn0);
                s[nb][1] = ex2f(s[nb][1] - mn0);
                s[nb][2] = ex2f(s[nb][2] - mn1);
                s[nb][3] = ex2f(s[nb][3] - mn1);
                sum0 += s[nb][0] + s[nb][1];
                sum1 += s[nb][2] + s[nb][3];
            }
            sum0 += __shfl_xor_sync(0xffffffffu, sum0, 1);
            sum0 += __shfl_xor_sync(0xffffffffu, sum0, 2);
            sum1 += __shfl_xor_sync(0xffffffffu, sum1, 1);
            sum1 += __shfl_xor_sync(0xffffffffu, sum1, 2);
            l0 = l0 * corr0 + sum0;
            l1 = l1 * corr1 + sum1;
            #pragma unroll
            for (int nd = 0; nd < 10; ++nd) {
                o[nd][0] *= corr0; o[nd][1] *= corr0;
                o[nd][2] *= corr1; o[nd][3] *= corr1;
            }

            // ---- P -> fp16 fragments (no split) ----
            uint32_t ph[4][4];
            #pragma unroll
            for (int kb = 0; kb < 4; ++kb) {
                ph[kb][0] = h2pack(s[2 * kb][0],     s[2 * kb][1]);
                ph[kb][1] = h2pack(s[2 * kb][2],     s[2 * kb][3]);
                ph[kb][2] = h2pack(s[2 * kb + 1][0], s[2 * kb + 1][1]);
                ph[kb][3] = h2pack(s[2 * kb + 1][2], s[2 * kb + 1][3]);
            }

            // ---- O += P V (fp16 single pass), two nd per ldsm.x4.trans ----
            #pragma unroll
            for (int nd2 = 0; nd2 < 5; ++nd2) {
                float* oA = o[nd2 * 2];
                float* oB = o[nd2 * 2 + 1];
                const uint32_t cbase = st + 11264 + (uint32_t)(nd2 * 32) + vrow;
                #pragma unroll
                for (int kb = 0; kb < 4; ++kb) {
                    uint32_t v4[4];
                    ldsm4t(v4, cbase + (uint32_t)(kb * 16 * 176));
                    mma16816h(oA, ph[kb], v4[0], v4[1]);
                    mma16816h(oB, ph[kb], v4[2], v4[3]);
                }
            }
        }
        __syncthreads();
    }

    // Epilogue: normalize + write ctx as bf16 hi/lo (for the bf16x3 GEMM2)
    const float inv0 = 1.f / l0, inv1 = 1.f / l1;
    const int r0 = qt * 128 + wm + (lane >> 2);
    #pragma unroll
    for (int nd = 0; nd < 10; ++nd) {
        const int col = h * HD_ + nd * 8 + (lane & 3) * 2;
        uint32_t hi, lo;
        split2(o[nd][0] * inv0, o[nd][1] * inv0, hi, lo);
        *(uint32_t*)&chi[((size_t)(b * S_ + r0)) * D_ + col] = hi;
        *(uint32_t*)&clo[((size_t)(b * S_ + r0)) * D_ + col] = lo;
        split2(o[nd][2] * inv1, o[nd][3] * inv1, hi, lo);
        *(uint32_t*)&chi[((size_t)(b * S_ + r0 + 8)) * D_ + col] = hi;
        *(uint32_t*)&clo[((size_t)(b * S_ + r0 + 8)) * D_ + col] = lo;
    }
}

// ---------------------------------------------------------------------------
// Launch
// ---------------------------------------------------------------------------
extern "C" void kernel_launch(void* const* d_in, const int* in_sizes, int n_in,
                              void* d_out, int out_size)
{
    const float* x      = (const float*)d_in[0];
    const float* wqkv_w = (const float*)d_in[1];
    const float* wqkv_b = (const float*)d_in[2];
    const float* out_w  = (const float*)d_in[3];
    const float* out_b  = (const float*)d_in[4];
    float* out = (float*)d_out;

    float* qkv;
    __nv_bfloat16 *ahi, *alo, *whi, *wlo, *ohi, *olo;
    __half *qf, *kf, *vf;
    cudaGetSymbolAddress((void**)&qkv, g_qkv);
    cudaGetSymbolAddress((void**)&ahi, g_ahi);
    cudaGetSymbolAddress((void**)&alo, g_alo);
    cudaGetSymbolAddress((void**)&whi, g_whi);
    cudaGetSymbolAddress((void**)&wlo, g_wlo);
    cudaGetSymbolAddress((void**)&ohi, g_ohi);
    cudaGetSymbolAddress((void**)&olo, g_olo);
    cudaGetSymbolAddress((void**)&qf, g_qf);
    cudaGetSymbolAddress((void**)&kf, g_kf);
    cudaGetSymbolAddress((void**)&vf, g_vf);

    cudaFuncSetAttribute(gemm_hmma,
                         cudaFuncAttributeMaxDynamicSharedMemorySize, GEMM_SMEM);
    cudaFuncSetAttribute(attn_tc,
                         cudaFuncAttributeMaxDynamicSharedMemorySize, ATTN_SMEM);

    // 0) rope table + split x / weights into bf16 hi/lo
    rope_table_kernel<<<S_ * 16 / 256, 256>>>();
    {
        const int n4x = M_ROWS * D_ / 4;
        cvt_split<<<n4x / 256, 256>>>((const float4*)x, (uint2*)ahi, (uint2*)alo, n4x);
        const int n4w = QKV_N * D_ / 4;
        cvt_split<<<n4w / 256, 256>>>((const float4*)wqkv_w, (uint2*)whi, (uint2*)wlo, n4w);
        const int n4o = D_ * D_ / 4;
        cvt_split<<<n4o / 256, 256>>>((const float4*)out_w, (uint2*)ohi, (uint2*)olo, n4o);
    }

    // 1) QKV = X @ Wqkv^T + b
    dim3 g1(QKV_N / 128, M_ROWS / 128);
    gemm_hmma<<<g1, 256, GEMM_SMEM>>>(ahi, alo, whi, wlo, wqkv_b, qkv,
                                      M_ROWS, QKV_N, D_);

    // 2) fused RoPE(table) + scale + convert qkv -> head-major fp16
    cvt_qkv<<<(M_ROWS * QKV_N / 4) / 256, 256>>>((const float4*)qkv);

    // 3) causal attention (fp16) -> ctx (written as bf16 hi/lo into ahi/alo)
    dim3 ga(S_ / 128, H_, B_);
    attn_tc<<<ga, 256, ATTN_SMEM>>>(qf, kf, vf, ahi, alo);

    // 4) out = ctx @ Wout^T + b
    dim3 g2(D_ / 128, M_ROWS / 128);
    gemm_hmma<<<g2, 256, GEMM_SMEM>>>(ahi, alo, ohi, olo, out_b, out,
                                      M_ROWS, D_, D_);
}

// round 16
// speedup vs baseline: 2.8195x; 1.5968x over previous
#include <cuda_runtime.h>
#include <cuda_bf16.h>
#include <cuda_fp16.h>
#include <cstdint>

// Problem constants
#define B_  2
#define S_  2048
#define D_  2560
#define H_  32
#define HD_ 80
#define RD_ 32

constexpr int M_ROWS = B_ * S_;       // 4096
constexpr int QKV_N  = 3 * D_;        // 7680

// Scratch (no allocation allowed -> __device__ globals)
__device__ float g_qkv[(size_t)M_ROWS * QKV_N];   // fp32 qkv from GEMM1
__device__ float g_rope_tab[S_ * 32];             // [s][0..15]=cos, [16..31]=sin
// bf16 hi/lo split operands (GEMM2: ctx + out_w)
__device__ __align__(256) __nv_bfloat16 g_ahi[(size_t)M_ROWS * D_];   // ctx
__device__ __align__(256) __nv_bfloat16 g_alo[(size_t)M_ROWS * D_];
__device__ __align__(256) __nv_bfloat16 g_ohi[(size_t)D_ * D_];
__device__ __align__(256) __nv_bfloat16 g_olo[(size_t)D_ * D_];
// fp16 operands for GEMM1
__device__ __align__(256) __half g_xf[(size_t)M_ROWS * D_];
__device__ __align__(256) __half g_wf[(size_t)QKV_N  * D_];
// head-major fp16 q/k/v: [b][h][s][80]
constexpr size_t HM_SZ = (size_t)B_ * H_ * S_ * HD_;
__device__ __align__(256) __half g_qf[HM_SZ];
__device__ __align__(256) __half g_kf[HM_SZ];
__device__ __align__(256) __half g_vf[HM_SZ];

// ---------------------------------------------------------------------------
// PTX helpers
// ---------------------------------------------------------------------------
__device__ __forceinline__ uint32_t smem_u32(const void* p) {
    uint32_t a;
    asm("{ .reg .u64 t; cvta.to.shared.u64 t, %1; cvt.u32.u64 %0, t; }"
        : "=r"(a) : "l"(p));
    return a;
}
__device__ __forceinline__ void ldsm4u(uint32_t* r, uint32_t addr) {
    asm volatile("ldmatrix.sync.aligned.m8n8.x4.shared.b16 {%0,%1,%2,%3}, [%4];"
                 : "=r"(r[0]), "=r"(r[1]), "=r"(r[2]), "=r"(r[3]) : "r"(addr));
}
__device__ __forceinline__ void ldsm4t(uint32_t* r, uint32_t addr) {
    asm volatile("ldmatrix.sync.aligned.m8n8.x4.trans.shared.b16 {%0,%1,%2,%3}, [%4];"
                 : "=r"(r[0]), "=r"(r[1]), "=r"(r[2]), "=r"(r[3]) : "r"(addr));
}
// bf16 HMMA (GEMM2)
__device__ __forceinline__ void mma16816(float* c, const uint32_t* a,
                                         uint32_t b0, uint32_t b1)
{
    asm volatile(
        "mma.sync.aligned.m16n8k16.row.col.f32.bf16.bf16.f32 "
        "{%0,%1,%2,%3}, {%4,%5,%6,%7}, {%8,%9}, {%0,%1,%2,%3};"
        : "+f"(c[0]), "+f"(c[1]), "+f"(c[2]), "+f"(c[3])
        : "r"(a[0]), "r"(a[1]), "r"(a[2]), "r"(a[3]), "r"(b0), "r"(b1));
}
// fp16 HMMA (GEMM1 + attention)
__device__ __forceinline__ void mma16816h(float* c, const uint32_t* a,
                                          uint32_t b0, uint32_t b1)
{
    asm volatile(
        "mma.sync.aligned.m16n8k16.row.col.f32.f16.f16.f32 "
        "{%0,%1,%2,%3}, {%4,%5,%6,%7}, {%8,%9}, {%0,%1,%2,%3};"
        : "+f"(c[0]), "+f"(c[1]), "+f"(c[2]), "+f"(c[3])
        : "r"(a[0]), "r"(a[1]), "r"(a[2]), "r"(a[3]), "r"(b0), "r"(b1));
}
__device__ __forceinline__ void cp_async16(uint32_t dst, const void* src) {
    asm volatile("cp.async.cg.shared.global [%0], [%1], 16;"
                 :: "r"(dst), "l"((unsigned long long)__cvta_generic_to_global(src)));
}
#define CP_COMMIT() asm volatile("cp.async.commit_group;" ::: "memory")

#define SWZ64(o) ((o) ^ (((o) >> 3) & 0x30))

__device__ __forceinline__ float ex2f(float x) {
    float r;
    asm("ex2.approx.f32 %0, %1;" : "=f"(r) : "f"(x));
    return r;
}

__device__ __forceinline__ void split2(float x, float y, uint32_t& hi, uint32_t& lo) {
    __nv_bfloat162 h = __floats2bfloat162_rn(x, y);
    float2 f = __bfloat1622float2(h);
    __nv_bfloat162 l = __floats2bfloat162_rn(x - f.x, y - f.y);
    hi = *(uint32_t*)&h;
    lo = *(uint32_t*)&l;
}
__device__ __forceinline__ void split4(float4 v, uint2& hi, uint2& lo) {
    split2(v.x, v.y, hi.x, lo.x);
    split2(v.z, v.w, hi.y, lo.y);
}
__device__ __forceinline__ uint32_t h2pack(float x, float y) {
    __half2 h = __floats2half2_rn(x, y);
    return *(uint32_t*)&h;
}

// ---------------------------------------------------------------------------
// fp32 -> bf16 hi/lo split (GEMM2 operands)
// ---------------------------------------------------------------------------
__global__ void cvt_split(const float4* __restrict__ in, uint2* __restrict__ hi,
                          uint2* __restrict__ lo, int n4)
{
    int i = blockIdx.x * blockDim.x + threadIdx.x;
    if (i >= n4) return;
    uint2 h, l;
    split4(in[i], h, l);
    hi[i] = h;
    lo[i] = l;
}

// ---------------------------------------------------------------------------
// fp32 -> fp16 convert (GEMM1 operands)
// ---------------------------------------------------------------------------
__global__ void cvt_h(const float4* __restrict__ in, uint2* __restrict__ out, int n4)
{
    int i = blockIdx.x * blockDim.x + threadIdx.x;
    if (i >= n4) return;
    float4 v = in[i];
    uint2 o;
    o.x = h2pack(v.x, v.y);
    o.y = h2pack(v.z, v.w);
    out[i] = o;
}

// ---------------------------------------------------------------------------
// RoPE cos/sin table (fp64 angle path, bit-matching the reference).
// ---------------------------------------------------------------------------
__global__ void rope_table_kernel()
{
    const int t = blockIdx.x * blockDim.x + threadIdx.x;   // 0..32767
    const int i = t & 15;
    const int s = t >> 4;
    const double inv = exp2(-(double)i * (13.287712379549449 / 16.0));
    const float ang  = (float)((double)s * inv);
    g_rope_tab[s * 32 + i]      = cosf(ang);
    g_rope_tab[s * 32 + 16 + i] = sinf(ang);
}

// ---------------------------------------------------------------------------
// Fused RoPE(table) + convert: qkv fp32 -> head-major fp16 q/k/v.
// q pre-scaled by (1/sqrt(80)) * log2(e) -> attention softmax in exp2 domain.
// ---------------------------------------------------------------------------
__global__ void cvt_qkv(const float4* __restrict__ qkv4)
{
    int idx = blockIdx.x * blockDim.x + threadIdx.x;
    const int n4 = M_ROWS * QKV_N / 4;
    if (idx >= n4) return;
    const int col4 = idx % (QKV_N / 4);
    const int rowm = idx / (QKV_N / 4);      // b*S + s
    const int col  = col4 * 4;
    const int part = col / D_;
    const int win  = col % D_;
    const int h    = win / HD_;
    const int d    = win % HD_;
    const int b    = rowm >> 11;
    const int s    = rowm & (S_ - 1);

    float4 v = qkv4[idx];

    if (part < 2 && d < RD_) {
        const bool first = (d < 16);
        const int  i     = first ? d : d - 16;
        const float4 cv  = *(const float4*)&g_rope_tab[s * 32 + i];
        const float4 sv  = *(const float4*)&g_rope_tab[s * 32 + 16 + i];
        const float4 ov  = qkv4[idx + (first ? 4 : -4)];
        if (first) {
            v.x = v.x * cv.x - ov.x * sv.x;
            v.y = v.y * cv.y - ov.y * sv.y;
            v.z = v.z * cv.z - ov.z * sv.z;
            v.w = v.w * cv.w - ov.w * sv.w;
        } else {
            v.x = ov.x * sv.x + v.x * cv.x;
            v.y = ov.y * sv.y + v.y * cv.y;
            v.z = ov.z * sv.z + v.z * cv.z;
            v.w = ov.w * sv.w + v.w * cv.w;
        }
    }
    if (part == 0) {   // fold softmax scale AND log2(e) into q
        const float scale = 0.11180339887498949f * 1.4426950408889634f;
        v.x *= scale; v.y *= scale; v.z *= scale; v.w *= scale;
    }

    uint2 hp;
    hp.x = h2pack(v.x, v.y);
    hp.y = h2pack(v.z, v.w);
    const size_t dst = (((size_t)(b * H_ + h)) * S_ + s) * HD_ + d;
    __half* pf = (part == 0) ? g_qf : (part == 1) ? g_kf : g_vf;
    *(uint2*)&pf[dst] = hp;
}

// ---------------------------------------------------------------------------
// fp16 single-pass NT GEMM (GEMM1): C[M,N] = A[M,K] @ W[N,K]^T + bias.
// Same verified structure as gemm_hmma: 128x128 CTA, warp 32x64, BK=32,
// 3-stage cp.async, single sync/stage. Stage = Ah(8K)+Bh(8K) = 16KB.
// ---------------------------------------------------------------------------
constexpr int GEMMH_SMEM = 3 * 16384;   // 49152

__global__ __launch_bounds__(256, 2)
void gemm_fp16(const __half* __restrict__ A, const __half* __restrict__ W,
               const float* __restrict__ bias, float* __restrict__ C,
               int M, int N, int K)
{
    extern __shared__ __align__(1024) char gsm[];
    const uint32_t sb = smem_u32(gsm);
    const int tid  = threadIdx.x;
    const int lane = tid & 31;
    const int wid  = tid >> 5;
    const int wm0  = (wid & 3) * 32;
    const int wn0  = (wid >> 2) * 64;
    const int bm   = blockIdx.y * 128;
    const int bn   = blockIdx.x * 128;
    const int lr   = lane & 7;
    const int g    = lane >> 3;

    const __half* s0 = A + (size_t)bm * K;
    const __half* s1 = W + (size_t)bn * K;

    float acc[2][8][4] = {};

    auto load_stage = [&](int s) {
        const uint32_t st = sb + (uint32_t)(s % 3) * 16384;
        #pragma unroll
        for (int it = 0; it < 4; ++it) {
            const int idx  = tid + it * 256;       // 0..1023
            const int tile = idx >> 9;             // 0=A, 1=B
            const int c    = idx & 511;
            const int row  = c >> 2;
            const int col  = c & 3;
            const __half* base = tile ? s1 : s0;
            cp_async16(st + tile * 8192 + SWZ64((uint32_t)(row * 64 + col * 16)),
                       base + (size_t)row * K + s * 32 + col * 8);
        }
        CP_COMMIT();
    };

    const int nst = K >> 5;
    load_stage(0);
    load_stage(1);

    for (int s = 0; s < nst; ++s) {
        if (s + 1 < nst)
            asm volatile("cp.async.wait_group 1;" ::: "memory");
        else
            asm volatile("cp.async.wait_group 0;" ::: "memory");
        __syncthreads();
        if (s + 2 < nst) load_stage(s + 2);

        const uint32_t st = sb + (uint32_t)(s % 3) * 16384;
        #pragma unroll
        for (int ks = 0; ks < 2; ++ks) {
            uint32_t ah[2][4];
            #pragma unroll
            for (int mi = 0; mi < 2; ++mi) {
                const uint32_t ro = (uint32_t)((wm0 + mi * 16 + lr + (g & 1) * 8) * 64
                                               + ks * 32 + (g >> 1) * 16);
                ldsm4u(ah[mi], st + SWZ64(ro));
            }
            #pragma unroll
            for (int np = 0; np < 4; ++np) {
                const uint32_t ro = (uint32_t)((wn0 + np * 16 + lr + (g >> 1) * 8) * 64
                                               + ks * 32 + (g & 1) * 16);
                uint32_t bh[4];
                ldsm4u(bh, st + 8192 + SWZ64(ro));
                #pragma unroll
                for (int half = 0; half < 2; ++half) {
                    const int ni = np * 2 + half;
                    #pragma unroll
                    for (int mi = 0; mi < 2; ++mi)
                        mma16816h(acc[mi][ni], ah[mi], bh[half * 2], bh[half * 2 + 1]);
                }
            }
        }
    }

    #pragma unroll
    for (int ni = 0; ni < 8; ++ni) {
        const int col = bn + wn0 + ni * 8 + (lane & 3) * 2;
        const float2 bv = *(const float2*)&bias[col];
        #pragma unroll
        for (int mi = 0; mi < 2; ++mi) {
            const int row = bm + wm0 + mi * 16 + (lane >> 2);
            *(float2*)&C[(size_t)row * N + col] =
                make_float2(acc[mi][ni][0] + bv.x, acc[mi][ni][1] + bv.y);
            *(float2*)&C[(size_t)(row + 8) * N + col] =
                make_float2(acc[mi][ni][2] + bv.x, acc[mi][ni][3] + bv.y);
        }
    }
}

// ---------------------------------------------------------------------------
// HMMA bf16x3 NT GEMM (GEMM2 -- verified, unchanged).
// ---------------------------------------------------------------------------
constexpr int GEMM_SMEM = 3 * 32768;

__global__ __launch_bounds__(256, 2)
void gemm_hmma(const __nv_bfloat16* __restrict__ Ahi, const __nv_bfloat16* __restrict__ Alo,
               const __nv_bfloat16* __restrict__ Bhi, const __nv_bfloat16* __restrict__ Blo,
               const float* __restrict__ bias, float* __restrict__ C,
               int M, int N, int K)
{
    extern __shared__ __align__(1024) char gsm[];
    const uint32_t sb = smem_u32(gsm);
    const int tid  = threadIdx.x;
    const int lane = tid & 31;
    const int wid  = tid >> 5;
    const int wm0  = (wid & 3) * 32;
    const int wn0  = (wid >> 2) * 64;
    const int bm   = blockIdx.y * 128;
    const int bn   = blockIdx.x * 128;
    const int lr   = lane & 7;
    const int g    = lane >> 3;

    const __nv_bfloat16* s0 = Ahi + (size_t)bm * K;
    const __nv_bfloat16* s1 = Alo + (size_t)bm * K;
    const __nv_bfloat16* s2 = Bhi + (size_t)bn * K;
    const __nv_bfloat16* s3 = Blo + (size_t)bn * K;

    float acc[2][8][4] = {};

    auto load_stage = [&](int s) {
        const uint32_t st = sb + (uint32_t)(s % 3) * 32768;
        #pragma unroll
        for (int it = 0; it < 8; ++it) {
            const int tile = it >> 1;
            const int idx  = tid + (it & 1) * 256;
            const int row  = idx >> 2;
            const int c    = idx & 3;
            const __nv_bfloat16* base =
                (tile == 0) ? s0 : (tile == 1) ? s1 : (tile == 2) ? s2 : s3;
            const __nv_bfloat16* gp = base + (size_t)row * K + s * 32 + c * 8;
            cp_async16(st + tile * 8192 + SWZ64((uint32_t)(row * 64 + c * 16)), gp);
        }
        CP_COMMIT();
    };

    const int nst = K >> 5;
    load_stage(0);
    load_stage(1);

    for (int s = 0; s < nst; ++s) {
        if (s + 1 < nst)
            asm volatile("cp.async.wait_group 1;" ::: "memory");
        else
            asm volatile("cp.async.wait_group 0;" ::: "memory");
        __syncthreads();
        if (s + 2 < nst) load_stage(s + 2);

        const uint32_t st = sb + (uint32_t)(s % 3) * 32768;
        #pragma unroll
        for (int ks = 0; ks < 2; ++ks) {
            uint32_t ah[2][4], al[2][4];
            #pragma unroll
            for (int mi = 0; mi < 2; ++mi) {
                const uint32_t ro = (uint32_t)((wm0 + mi * 16 + lr + (g & 1) * 8) * 64
                                               + ks * 32 + (g >> 1) * 16);
                ldsm4u(ah[mi], st + SWZ64(ro));
                ldsm4u(al[mi], st + 8192 + SWZ64(ro));
            }
            #pragma unroll
            for (int np = 0; np < 4; ++np) {
                const uint32_t ro = (uint32_t)((wn0 + np * 16 + lr + (g >> 1) * 8) * 64
                                               + ks * 32 + (g & 1) * 16);
                uint32_t bh[4], bl[4];
                ldsm4u(bh, st + 16384 + SWZ64(ro));
                ldsm4u(bl, st + 24576 + SWZ64(ro));
                #pragma unroll
                for (int half = 0; half < 2; ++half) {
                    const int ni = np * 2 + half;
                    #pragma unroll
                    for (int mi = 0; mi < 2; ++mi) {
                        mma16816(acc[mi][ni], ah[mi], bh[half * 2], bh[half * 2 + 1]);
                        mma16816(acc[mi][ni], ah[mi], bl[half * 2], bl[half * 2 + 1]);
                        mma16816(acc[mi][ni], al[mi], bh[half * 2], bh[half * 2 + 1]);
                    }
                }
            }
        }
    }

    #pragma unroll
    for (int ni = 0; ni < 8; ++ni) {
        const int col = bn + wn0 + ni * 8 + (lane & 3) * 2;
        const float2 bv = *(const float2*)&bias[col];
        #pragma unroll
        for (int mi = 0; mi < 2; ++mi) {
            const int row = bm + wm0 + mi * 16 + (lane >> 2);
            *(float2*)&C[(size_t)row * N + col] =
                make_float2(acc[mi][ni][0] + bv.x, acc[mi][ni][1] + bv.y);
            *(float2*)&C[(size_t)(row + 8) * N + col] =
                make_float2(acc[mi][ni][2] + bv.x, acc[mi][ni][3] + bv.y);
        }
    }
}

// ---------------------------------------------------------------------------
// Causal flash attention, fp16 single-pass HMMA (round-15 verified).
// ---------------------------------------------------------------------------
constexpr int ATTN_SMEM = 22528 + 2 * 22528;   // 67584

__global__ __launch_bounds__(256, 1)
void attn_tc(const __half* __restrict__ qf_g, const __half* __restrict__ kf_g,
             const __half* __restrict__ vf_g,
             __nv_bfloat16* __restrict__ chi, __nv_bfloat16* __restrict__ clo)
{
    extern __shared__ __align__(1024) char smc[];
    const uint32_t sb = smem_u32(smc);
    const int qt   = gridDim.x - 1 - blockIdx.x;   // big tiles first
    const int h    = blockIdx.y;
    const int b    = blockIdx.z;
    const int tid  = threadIdx.x;
    const int lane = tid & 31;
    const int wid  = tid >> 5;
    const int wm   = wid * 16;
    const int lr   = lane & 7;
    const int g    = lane >> 3;

    const size_t hb = ((size_t)(b * H_ + h)) * S_ * HD_;

    // ---- stage Q (fp16, 128 rows x 176B) and load fragments ----
    for (int t = tid; t < 1280; t += 256) {
        const int row = t / 10, c = t % 10;
        cp_async16(sb + (uint32_t)(row * 176 + c * 16),
                   qf_g + hb + (size_t)(qt * 128 + row) * HD_ + c * 8);
    }
    CP_COMMIT();
    asm volatile("cp.async.wait_group 0;" ::: "memory");
    __syncthreads();

    uint32_t qf[5][4];
    #pragma unroll
    for (int ks = 0; ks < 5; ++ks) {
        const uint32_t ro = (uint32_t)((wm + lr + (g & 1) * 8) * 176 + ks * 32 + (g >> 1) * 16);
        ldsm4u(qf[ks], sb + ro);
    }
    __syncthreads();

    const uint32_t KVB = sb + 22528;
    auto load_kv = [&](int kt) {
        const uint32_t st = KVB + (uint32_t)(kt & 1) * 22528;
        #pragma unroll
        for (int it = 0; it < 5; ++it) {
            const int t = tid + it * 256;            // 0..1279
            const int arr = t / 640, rem = t % 640;
            const int row = rem / 10, c = rem % 10;
            const __half* src = (arr ? vf_g : kf_g) + hb
                                + (size_t)(kt * 64 + row) * HD_ + c * 8;
            cp_async16(st + (uint32_t)(arr * 11264 + row * 176 + c * 16), src);
        }
        CP_COMMIT();
    };

    float o[10][4] = {};
    float mx0 = -1e30f, mx1 = -1e30f, l0 = 0.f, l1 = 0.f;
    const int nkt = 2 * qt + 2;

    load_kv(0);

    const uint32_t krow = (uint32_t)(((lane >> 4) * 8 + lr) * 176 + ((lane >> 3) & 1) * 16);
    const uint32_t vrow = (uint32_t)((((lane >> 3) & 1) * 8 + lr) * 176 + (lane >> 4) * 16);

    for (int kt = 0; kt < nkt; ++kt) {
        if (kt + 1 < nkt) {
            load_kv(kt + 1);
            asm volatile("cp.async.wait_group 1;" ::: "memory");
        } else {
            asm volatile("cp.async.wait_group 0;" ::: "memory");
        }
        __syncthreads();

        const bool active = (qt * 128 + wm + 15 >= kt * 64);
        if (active) {
            const uint32_t st = KVB + (uint32_t)(kt & 1) * 22528;

            // ---- scores S = Q K^T (fp16 single pass) ----
            float s[8][4];
            #pragma unroll
            for (int nb2 = 0; nb2 < 4; ++nb2) {
                float* sA = s[nb2 * 2];
                float* sB = s[nb2 * 2 + 1];
                sA[0] = sA[1] = sA[2] = sA[3] = 0.f;
                sB[0] = sB[1] = sB[2] = sB[3] = 0.f;
                const uint32_t rbase = st + (uint32_t)(nb2 * 16 * 176) + krow;
                #pragma unroll
                for (int ks = 0; ks < 5; ++ks) {
                    uint32_t k4[4];
                    ldsm4u(k4, rbase + ks * 32);
                    mma16816h(sA, qf[ks], k4[0], k4[1]);
                    mma16816h(sB, qf[ks], k4[2], k4[3]);
                }
            }
            if (kt >= 2 * qt) {   // diagonal-region mask
                const int r0 = qt * 128 + wm + (lane >> 2);
                #pragma unroll
                for (int nb = 0; nb < 8; ++nb) {
                    const int c0 = kt * 64 + nb * 8 + (lane & 3) * 2;
                    if (c0     > r0)     s[nb][0] = -1e30f;
                    if (c0 + 1 > r0)     s[nb][1] = -1e30f;
                    if (c0     > r0 + 8) s[nb][2] = -1e30f;
                    if (c0 + 1 > r0 + 8) s[nb][3] = -1e30f;
                }
            }

            // ---- online softmax (exp2 domain) ----
            float m0 = -1e30f, m1 = -1e30f;
            #pragma unroll
            for (int nb = 0; nb < 8; ++nb) {
                m0 = fmaxf(m0, fmaxf(s[nb][0], s[nb][1]));
                m1 = fmaxf(m1, fmaxf(s[nb][2], s[nb][3]));
            }
            m0 = fmaxf(m0, __shfl_xor_sync(0xffffffffu, m0, 1));
            m0 = fmaxf(m0, __shfl_xor_sync(0xffffffffu, m0, 2));
            m1 = fmaxf(m1, __shfl_xor_sync(0xffffffffu, m1, 1));
            m1 = fmaxf(m1, __shfl_xor_sync(0xffffffffu, m1, 2));
            const float mn0 = fmaxf(mx0, m0), mn1 = fmaxf(mx1, m1);
            const float corr0 = ex2f(mx0 - mn0), corr1 = ex2f(mx1 - mn1);
            mx0 = mn0; mx1 = mn1;
            float sum0 = 0.f, sum1 = 0.f;
            #pragma unroll
            for (int nb = 0; nb < 8; ++nb) {
                s[nb][0] = ex2f(s[nb][0] - mn0);
                s[nb][1] = ex2f(s[nb][1] - mn0);
                s[nb][2] = ex2f(s[nb][2] - mn1);
                s[nb][3] = ex2f(s[nb][3] - mn1);
                sum0 += s[nb][0] + s[nb][1];
                sum1 += s[nb][2] + s[nb][3];
            }
            sum0 += __shfl_xor_sync(0xffffffffu, sum0, 1);
            sum0 += __shfl_xor_sync(0xffffffffu, sum0, 2);
            sum1 += __shfl_xor_sync(0xffffffffu, sum1, 1);
            sum1 += __shfl_xor_sync(0xffffffffu, sum1, 2);
            l0 = l0 * corr0 + sum0;
            l1 = l1 * corr1 + sum1;
            #pragma unroll
            for (int nd = 0; nd < 10; ++nd) {
                o[nd][0] *= corr0; o[nd][1] *= corr0;
                o[nd][2] *= corr1; o[nd][3] *= corr1;
            }

            // ---- P -> fp16 fragments ----
            uint32_t ph[4][4];
            #pragma unroll
            for (int kb = 0; kb < 4; ++kb) {
                ph[kb][0] = h2pack(s[2 * kb][0],     s[2 * kb][1]);
                ph[kb][1] = h2pack(s[2 * kb][2],     s[2 * kb][3]);
                ph[kb][2] = h2pack(s[2 * kb + 1][0], s[2 * kb + 1][1]);
                ph[kb][3] = h2pack(s[2 * kb + 1][2], s[2 * kb + 1][3]);
            }

            // ---- O += P V (fp16 single pass) ----
            #pragma unroll
            for (int nd2 = 0; nd2 < 5; ++nd2) {
                float* oA = o[nd2 * 2];
                float* oB = o[nd2 * 2 + 1];
                const uint32_t cbase = st + 11264 + (uint32_t)(nd2 * 32) + vrow;
                #pragma unroll
                for (int kb = 0; kb < 4; ++kb) {
                    uint32_t v4[4];
                    ldsm4t(v4, cbase + (uint32_t)(kb * 16 * 176));
                    mma16816h(oA, ph[kb], v4[0], v4[1]);
                    mma16816h(oB, ph[kb], v4[2], v4[3]);
                }
            }
        }
        __syncthreads();
    }

    // Epilogue: normalize + write ctx as bf16 hi/lo (for the bf16x3 GEMM2)
    const float inv0 = 1.f / l0, inv1 = 1.f / l1;
    const int r0 = qt * 128 + wm + (lane >> 2);
    #pragma unroll
    for (int nd = 0; nd < 10; ++nd) {
        const int col = h * HD_ + nd * 8 + (lane & 3) * 2;
        uint32_t hi, lo;
        split2(o[nd][0] * inv0, o[nd][1] * inv0, hi, lo);
        *(uint32_t*)&chi[((size_t)(b * S_ + r0)) * D_ + col] = hi;
        *(uint32_t*)&clo[((size_t)(b * S_ + r0)) * D_ + col] = lo;
        split2(o[nd][2] * inv1, o[nd][3] * inv1, hi, lo);
        *(uint32_t*)&chi[((size_t)(b * S_ + r0 + 8)) * D_ + col] = hi;
        *(uint32_t*)&clo[((size_t)(b * S_ + r0 + 8)) * D_ + col] = lo;
    }
}

// ---------------------------------------------------------------------------
// Launch
// ---------------------------------------------------------------------------
extern "C" void kernel_launch(void* const* d_in, const int* in_sizes, int n_in,
                              void* d_out, int out_size)
{
    const float* x      = (const float*)d_in[0];
    const float* wqkv_w = (const float*)d_in[1];
    const float* wqkv_b = (const float*)d_in[2];
    const float* out_w  = (const float*)d_in[3];
    const float* out_b  = (const float*)d_in[4];
    float* out = (float*)d_out;

    float* qkv;
    __nv_bfloat16 *ahi, *alo, *ohi, *olo;
    __half *xf, *wf, *qf, *kf, *vf;
    cudaGetSymbolAddress((void**)&qkv, g_qkv);
    cudaGetSymbolAddress((void**)&ahi, g_ahi);
    cudaGetSymbolAddress((void**)&alo, g_alo);
    cudaGetSymbolAddress((void**)&ohi, g_ohi);
    cudaGetSymbolAddress((void**)&olo, g_olo);
    cudaGetSymbolAddress((void**)&xf, g_xf);
    cudaGetSymbolAddress((void**)&wf, g_wf);
    cudaGetSymbolAddress((void**)&qf, g_qf);
    cudaGetSymbolAddress((void**)&kf, g_kf);
    cudaGetSymbolAddress((void**)&vf, g_vf);

    cudaFuncSetAttribute(gemm_fp16,
                         cudaFuncAttributeMaxDynamicSharedMemorySize, GEMMH_SMEM);
    cudaFuncSetAttribute(gemm_hmma,
                         cudaFuncAttributeMaxDynamicSharedMemorySize, GEMM_SMEM);
    cudaFuncSetAttribute(attn_tc,
                         cudaFuncAttributeMaxDynamicSharedMemorySize, ATTN_SMEM);

    // 0) rope table + fp16 converts (GEMM1) + bf16 split of out_w (GEMM2)
    rope_table_kernel<<<S_ * 16 / 256, 256>>>();
    {
        const int n4x = M_ROWS * D_ / 4;
        cvt_h<<<n4x / 256, 256>>>((const float4*)x, (uint2*)xf, n4x);
        const int n4w = QKV_N * D_ / 4;
        cvt_h<<<n4w / 256, 256>>>((const float4*)wqkv_w, (uint2*)wf, n4w);
        const int n4o = D_ * D_ / 4;
        cvt_split<<<n4o / 256, 256>>>((const float4*)out_w, (uint2*)ohi, (uint2*)olo, n4o);
    }

    // 1) QKV = X @ Wqkv^T + b   (fp16 single-pass)
    dim3 g1(QKV_N / 128, M_ROWS / 128);
    gemm_fp16<<<g1, 256, GEMMH_SMEM>>>(xf, wf, wqkv_b, qkv, M_ROWS, QKV_N, D_);

    // 2) fused RoPE(table) + scale + convert qkv -> head-major fp16
    cvt_qkv<<<(M_ROWS * QKV_N / 4) / 256, 256>>>((const float4*)qkv);

    // 3) causal attention (fp16) -> ctx (written as bf16 hi/lo into ahi/alo)
    dim3 ga(S_ / 128, H_, B_);
    attn_tc<<<ga, 256, ATTN_SMEM>>>(qf, kf, vf, ahi, alo);

    // 4) out = ctx @ Wout^T + b   (bf16x3, keeps precision margin)
    dim3 g2(D_ / 128, M_ROWS / 128);
    gemm_hmma<<<g2, 256, GEMM_SMEM>>>(ahi, alo, ohi, olo, out_b, out,
                                      M_ROWS, D_, D_);
}

// round 17
// speedup vs baseline: 3.6838x; 1.3065x over previous
#include <cuda_runtime.h>
#include <cuda_fp16.h>
#include <cstdint>

// Problem constants
#define B_  2
#define S_  2048
#define D_  2560
#define H_  32
#define HD_ 80
#define RD_ 32

constexpr int M_ROWS = B_ * S_;       // 4096
constexpr int QKV_N  = 3 * D_;        // 7680

// Scratch (no allocation allowed -> __device__ globals)
__device__ float g_qkv[(size_t)M_ROWS * QKV_N];   // fp32 qkv from GEMM1
__device__ float g_rope_tab[S_ * 32];             // [s][0..15]=cos, [16..31]=sin
// fp16 operands
__device__ __align__(256) __half g_xf[(size_t)M_ROWS * D_];   // x (GEMM1 A)
__device__ __align__(256) __half g_wf[(size_t)QKV_N  * D_];   // wqkv (GEMM1 B)
__device__ __align__(256) __half g_cf[(size_t)M_ROWS * D_];   // ctx (GEMM2 A)
__device__ __align__(256) __half g_of[(size_t)D_ * D_];       // out_w (GEMM2 B)
// head-major fp16 q/k/v: [b][h][s][80]
constexpr size_t HM_SZ = (size_t)B_ * H_ * S_ * HD_;
__device__ __align__(256) __half g_qf[HM_SZ];
__device__ __align__(256) __half g_kf[HM_SZ];
__device__ __align__(256) __half g_vf[HM_SZ];

// ---------------------------------------------------------------------------
// PTX helpers
// ---------------------------------------------------------------------------
__device__ __forceinline__ uint32_t smem_u32(const void* p) {
    uint32_t a;
    asm("{ .reg .u64 t; cvta.to.shared.u64 t, %1; cvt.u32.u64 %0, t; }"
        : "=r"(a) : "l"(p));
    return a;
}
__device__ __forceinline__ void ldsm4u(uint32_t* r, uint32_t addr) {
    asm volatile("ldmatrix.sync.aligned.m8n8.x4.shared.b16 {%0,%1,%2,%3}, [%4];"
                 : "=r"(r[0]), "=r"(r[1]), "=r"(r[2]), "=r"(r[3]) : "r"(addr));
}
__device__ __forceinline__ void ldsm4t(uint32_t* r, uint32_t addr) {
    asm volatile("ldmatrix.sync.aligned.m8n8.x4.trans.shared.b16 {%0,%1,%2,%3}, [%4];"
                 : "=r"(r[0]), "=r"(r[1]), "=r"(r[2]), "=r"(r[3]) : "r"(addr));
}
__device__ __forceinline__ void mma16816h(float* c, const uint32_t* a,
                                          uint32_t b0, uint32_t b1)
{
    asm volatile(
        "mma.sync.aligned.m16n8k16.row.col.f32.f16.f16.f32 "
        "{%0,%1,%2,%3}, {%4,%5,%6,%7}, {%8,%9}, {%0,%1,%2,%3};"
        : "+f"(c[0]), "+f"(c[1]), "+f"(c[2]), "+f"(c[3])
        : "r"(a[0]), "r"(a[1]), "r"(a[2]), "r"(a[3]), "r"(b0), "r"(b1));
}
__device__ __forceinline__ void cp_async16(uint32_t dst, const void* src) {
    asm volatile("cp.async.cg.shared.global [%0], [%1], 16;"
                 :: "r"(dst), "l"((unsigned long long)__cvta_generic_to_global(src)));
}
#define CP_COMMIT() asm volatile("cp.async.commit_group;" ::: "memory")

#define SWZ64(o) ((o) ^ (((o) >> 3) & 0x30))

__device__ __forceinline__ float ex2f(float x) {
    float r;
    asm("ex2.approx.f32 %0, %1;" : "=f"(r) : "f"(x));
    return r;
}
__device__ __forceinline__ uint32_t h2pack(float x, float y) {
    __half2 h = __floats2half2_rn(x, y);
    return *(uint32_t*)&h;
}

// ---------------------------------------------------------------------------
// fp32 -> fp16 convert (GEMM operands)
// ---------------------------------------------------------------------------
__global__ void cvt_h(const float4* __restrict__ in, uint2* __restrict__ out, int n4)
{
    int i = blockIdx.x * blockDim.x + threadIdx.x;
    if (i >= n4) return;
    float4 v = in[i];
    uint2 o;
    o.x = h2pack(v.x, v.y);
    o.y = h2pack(v.z, v.w);
    out[i] = o;
}

// ---------------------------------------------------------------------------
// RoPE cos/sin table (fp64 angle path, bit-matching the reference).
// ---------------------------------------------------------------------------
__global__ void rope_table_kernel()
{
    const int t = blockIdx.x * blockDim.x + threadIdx.x;   // 0..32767
    const int i = t & 15;
    const int s = t >> 4;
    const double inv = exp2(-(double)i * (13.287712379549449 / 16.0));
    const float ang  = (float)((double)s * inv);
    g_rope_tab[s * 32 + i]      = cosf(ang);
    g_rope_tab[s * 32 + 16 + i] = sinf(ang);
}

// ---------------------------------------------------------------------------
// Fused RoPE(table) + convert: qkv fp32 -> head-major fp16 q/k/v.
// q pre-scaled by (1/sqrt(80)) * log2(e) -> attention softmax in exp2 domain.
// ---------------------------------------------------------------------------
__global__ void cvt_qkv(const float4* __restrict__ qkv4)
{
    int idx = blockIdx.x * blockDim.x + threadIdx.x;
    const int n4 = M_ROWS * QKV_N / 4;
    if (idx >= n4) return;
    const int col4 = idx % (QKV_N / 4);
    const int rowm = idx / (QKV_N / 4);      // b*S + s
    const int col  = col4 * 4;
    const int part = col / D_;
    const int win  = col % D_;
    const int h    = win / HD_;
    const int d    = win % HD_;
    const int b    = rowm >> 11;
    const int s    = rowm & (S_ - 1);

    float4 v = qkv4[idx];

    if (part < 2 && d < RD_) {
        const bool first = (d < 16);
        const int  i     = first ? d : d - 16;
        const float4 cv  = *(const float4*)&g_rope_tab[s * 32 + i];
        const float4 sv  = *(const float4*)&g_rope_tab[s * 32 + 16 + i];
        const float4 ov  = qkv4[idx + (first ? 4 : -4)];
        if (first) {
            v.x = v.x * cv.x - ov.x * sv.x;
            v.y = v.y * cv.y - ov.y * sv.y;
            v.z = v.z * cv.z - ov.z * sv.z;
            v.w = v.w * cv.w - ov.w * sv.w;
        } else {
            v.x = ov.x * sv.x + v.x * cv.x;
            v.y = ov.y * sv.y + v.y * cv.y;
            v.z = ov.z * sv.z + v.z * cv.z;
            v.w = ov.w * sv.w + v.w * cv.w;
        }
    }
    if (part == 0) {   // fold softmax scale AND log2(e) into q
        const float scale = 0.11180339887498949f * 1.4426950408889634f;
        v.x *= scale; v.y *= scale; v.z *= scale; v.w *= scale;
    }

    uint2 hp;
    hp.x = h2pack(v.x, v.y);
    hp.y = h2pack(v.z, v.w);
    const size_t dst = (((size_t)(b * H_ + h)) * S_ + s) * HD_ + d;
    __half* pf = (part == 0) ? g_qf : (part == 1) ? g_kf : g_vf;
    *(uint2*)&pf[dst] = hp;
}

// ---------------------------------------------------------------------------
// fp16 single-pass NT GEMM: C[M,N] = A[M,K] @ W[N,K]^T + bias.
// 128x128 CTA, warp 32x64, BK=32, 3-stage cp.async, single sync/stage.
// (round-16 verified structure; now used for BOTH projections)
// ---------------------------------------------------------------------------
constexpr int GEMMH_SMEM = 3 * 16384;   // 49152

__global__ __launch_bounds__(256, 2)
void gemm_fp16(const __half* __restrict__ A, const __half* __restrict__ W,
               const float* __restrict__ bias, float* __restrict__ C,
               int M, int N, int K)
{
    extern __shared__ __align__(1024) char gsm[];
    const uint32_t sb = smem_u32(gsm);
    const int tid  = threadIdx.x;
    const int lane = tid & 31;
    const int wid  = tid >> 5;
    const int wm0  = (wid & 3) * 32;
    const int wn0  = (wid >> 2) * 64;
    const int bm   = blockIdx.y * 128;
    const int bn   = blockIdx.x * 128;
    const int lr   = lane & 7;
    const int g    = lane >> 3;

    const __half* s0 = A + (size_t)bm * K;
    const __half* s1 = W + (size_t)bn * K;

    float acc[2][8][4] = {};

    auto load_stage = [&](int s) {
        const uint32_t st = sb + (uint32_t)(s % 3) * 16384;
        #pragma unroll
        for (int it = 0; it < 4; ++it) {
            const int idx  = tid + it * 256;       // 0..1023
            const int tile = idx >> 9;             // 0=A, 1=B
            const int c    = idx & 511;
            const int row  = c >> 2;
            const int col  = c & 3;
            const __half* base = tile ? s1 : s0;
            cp_async16(st + tile * 8192 + SWZ64((uint32_t)(row * 64 + col * 16)),
                       base + (size_t)row * K + s * 32 + col * 8);
        }
        CP_COMMIT();
    };

    const int nst = K >> 5;
    load_stage(0);
    load_stage(1);

    for (int s = 0; s < nst; ++s) {
        if (s + 1 < nst)
            asm volatile("cp.async.wait_group 1;" ::: "memory");
        else
            asm volatile("cp.async.wait_group 0;" ::: "memory");
        __syncthreads();
        if (s + 2 < nst) load_stage(s + 2);

        const uint32_t st = sb + (uint32_t)(s % 3) * 16384;
        #pragma unroll
        for (int ks = 0; ks < 2; ++ks) {
            uint32_t ah[2][4];
            #pragma unroll
            for (int mi = 0; mi < 2; ++mi) {
                const uint32_t ro = (uint32_t)((wm0 + mi * 16 + lr + (g & 1) * 8) * 64
                                               + ks * 32 + (g >> 1) * 16);
                ldsm4u(ah[mi], st + SWZ64(ro));
            }
            #pragma unroll
            for (int np = 0; np < 4; ++np) {
                const uint32_t ro = (uint32_t)((wn0 + np * 16 + lr + (g >> 1) * 8) * 64
                                               + ks * 32 + (g & 1) * 16);
                uint32_t bh[4];
                ldsm4u(bh, st + 8192 + SWZ64(ro));
                #pragma unroll
                for (int half = 0; half < 2; ++half) {
                    const int ni = np * 2 + half;
                    #pragma unroll
                    for (int mi = 0; mi < 2; ++mi)
                        mma16816h(acc[mi][ni], ah[mi], bh[half * 2], bh[half * 2 + 1]);
                }
            }
        }
    }

    #pragma unroll
    for (int ni = 0; ni < 8; ++ni) {
        const int col = bn + wn0 + ni * 8 + (lane & 3) * 2;
        const float2 bv = *(const float2*)&bias[col];
        #pragma unroll
        for (int mi = 0; mi < 2; ++mi) {
            const int row = bm + wm0 + mi * 16 + (lane >> 2);
            *(float2*)&C[(size_t)row * N + col] =
                make_float2(acc[mi][ni][0] + bv.x, acc[mi][ni][1] + bv.y);
            *(float2*)&C[(size_t)(row + 8) * N + col] =
                make_float2(acc[mi][ni][2] + bv.x, acc[mi][ni][3] + bv.y);
        }
    }
}

// ---------------------------------------------------------------------------
// Causal flash attention, fp16 single-pass HMMA (round-15 verified structure).
// Epilogue writes ctx directly as fp16 (GEMM2 operand).
// ---------------------------------------------------------------------------
constexpr int ATTN_SMEM = 22528 + 2 * 22528;   // 67584

__global__ __launch_bounds__(256, 1)
void attn_tc(const __half* __restrict__ qf_g, const __half* __restrict__ kf_g,
             const __half* __restrict__ vf_g, __half* __restrict__ ctxf)
{
    extern __shared__ __align__(1024) char smc[];
    const uint32_t sb = smem_u32(smc);
    const int qt   = gridDim.x - 1 - blockIdx.x;   // big tiles first
    const int h    = blockIdx.y;
    const int b    = blockIdx.z;
    const int tid  = threadIdx.x;
    const int lane = tid & 31;
    const int wid  = tid >> 5;
    const int wm   = wid * 16;
    const int lr   = lane & 7;
    const int g    = lane >> 3;

    const size_t hb = ((size_t)(b * H_ + h)) * S_ * HD_;

    // ---- stage Q (fp16, 128 rows x 176B) and load fragments ----
    for (int t = tid; t < 1280; t += 256) {
        const int row = t / 10, c = t % 10;
        cp_async16(sb + (uint32_t)(row * 176 + c * 16),
                   qf_g + hb + (size_t)(qt * 128 + row) * HD_ + c * 8);
    }
    CP_COMMIT();
    asm volatile("cp.async.wait_group 0;" ::: "memory");
    __syncthreads();

    uint32_t qf[5][4];
    #pragma unroll
    for (int ks = 0; ks < 5; ++ks) {
        const uint32_t ro = (uint32_t)((wm + lr + (g & 1) * 8) * 176 + ks * 32 + (g >> 1) * 16);
        ldsm4u(qf[ks], sb + ro);
    }
    __syncthreads();

    const uint32_t KVB = sb + 22528;
    auto load_kv = [&](int kt) {
        const uint32_t st = KVB + (uint32_t)(kt & 1) * 22528;
        #pragma unroll
        for (int it = 0; it < 5; ++it) {
            const int t = tid + it * 256;            // 0..1279
            const int arr = t / 640, rem = t % 640;
            const int row = rem / 10, c = rem % 10;
            const __half* src = (arr ? vf_g : kf_g) + hb
                                + (size_t)(kt * 64 + row) * HD_ + c * 8;
            cp_async16(st + (uint32_t)(arr * 11264 + row * 176 + c * 16), src);
        }
        CP_COMMIT();
    };

    float o[10][4] = {};
    float mx0 = -1e30f, mx1 = -1e30f, l0 = 0.f, l1 = 0.f;
    const int nkt = 2 * qt + 2;

    load_kv(0);

    const uint32_t krow = (uint32_t)(((lane >> 4) * 8 + lr) * 176 + ((lane >> 3) & 1) * 16);
    const uint32_t vrow = (uint32_t)((((lane >> 3) & 1) * 8 + lr) * 176 + (lane >> 4) * 16);

    for (int kt = 0; kt < nkt; ++kt) {
        if (kt + 1 < nkt) {
            load_kv(kt + 1);
            asm volatile("cp.async.wait_group 1;" ::: "memory");
        } else {
            asm volatile("cp.async.wait_group 0;" ::: "memory");
        }
        __syncthreads();

        const bool active = (qt * 128 + wm + 15 >= kt * 64);
        if (active) {
            const uint32_t st = KVB + (uint32_t)(kt & 1) * 22528;

            // ---- scores S = Q K^T ----
            float s[8][4];
            #pragma unroll
            for (int nb2 = 0; nb2 < 4; ++nb2) {
                float* sA = s[nb2 * 2];
                float* sB = s[nb2 * 2 + 1];
                sA[0] = sA[1] = sA[2] = sA[3] = 0.f;
                sB[0] = sB[1] = sB[2] = sB[3] = 0.f;
                const uint32_t rbase = st + (uint32_t)(nb2 * 16 * 176) + krow;
                #pragma unroll
                for (int ks = 0; ks < 5; ++ks) {
                    uint32_t k4[4];
                    ldsm4u(k4, rbase + ks * 32);
                    mma16816h(sA, qf[ks], k4[0], k4[1]);
                    mma16816h(sB, qf[ks], k4[2], k4[3]);
                }
            }
            if (kt >= 2 * qt) {   // diagonal-region mask
                const int r0 = qt * 128 + wm + (lane >> 2);
                #pragma unroll
                for (int nb = 0; nb < 8; ++nb) {
                    const int c0 = kt * 64 + nb * 8 + (lane & 3) * 2;
                    if (c0     > r0)     s[nb][0] = -1e30f;
                    if (c0 + 1 > r0)     s[nb][1] = -1e30f;
                    if (c0     > r0 + 8) s[nb][2] = -1e30f;
                    if (c0 + 1 > r0 + 8) s[nb][3] = -1e30f;
                }
            }

            // ---- online softmax (exp2 domain) ----
            float m0 = -1e30f, m1 = -1e30f;
            #pragma unroll
            for (int nb = 0; nb < 8; ++nb) {
                m0 = fmaxf(m0, fmaxf(s[nb][0], s[nb][1]));
                m1 = fmaxf(m1, fmaxf(s[nb][2], s[nb][3]));
            }
            m0 = fmaxf(m0, __shfl_xor_sync(0xffffffffu, m0, 1));
            m0 = fmaxf(m0, __shfl_xor_sync(0xffffffffu, m0, 2));
            m1 = fmaxf(m1, __shfl_xor_sync(0xffffffffu, m1, 1));
            m1 = fmaxf(m1, __shfl_xor_sync(0xffffffffu, m1, 2));
            const float mn0 = fmaxf(mx0, m0), mn1 = fmaxf(mx1, m1);
            const float corr0 = ex2f(mx0 - mn0), corr1 = ex2f(mx1 - mn1);
            mx0 = mn0; mx1 = mn1;
            float sum0 = 0.f, sum1 = 0.f;
            #pragma unroll
            for (int nb = 0; nb < 8; ++nb) {
                s[nb][0] = ex2f(s[nb][0] - mn0);
                s[nb][1] = ex2f(s[nb][1] - mn0);
                s[nb][2] = ex2f(s[nb][2] - mn1);
                s[nb][3] = ex2f(s[nb][3] - mn1);
                sum0 += s[nb][0] + s[nb][1];
                sum1 += s[nb][2] + s[nb][3];
            }
            sum0 += __shfl_xor_sync(0xffffffffu, sum0, 1);
            sum0 += __shfl_xor_sync(0xffffffffu, sum0, 2);
            sum1 += __shfl_xor_sync(0xffffffffu, sum1, 1);
            sum1 += __shfl_xor_sync(0xffffffffu, sum1, 2);
            l0 = l0 * corr0 + sum0;
            l1 = l1 * corr1 + sum1;
            #pragma unroll
            for (int nd = 0; nd < 10; ++nd) {
                o[nd][0] *= corr0; o[nd][1] *= corr0;
                o[nd][2] *= corr1; o[nd][3] *= corr1;
            }

            // ---- P -> fp16 fragments ----
            uint32_t ph[4][4];
            #pragma unroll
            for (int kb = 0; kb < 4; ++kb) {
                ph[kb][0] = h2pack(s[2 * kb][0],     s[2 * kb][1]);
                ph[kb][1] = h2pack(s[2 * kb][2],     s[2 * kb][3]);
                ph[kb][2] = h2pack(s[2 * kb + 1][0], s[2 * kb + 1][1]);
                ph[kb][3] = h2pack(s[2 * kb + 1][2], s[2 * kb + 1][3]);
            }

            // ---- O += P V ----
            #pragma unroll
            for (int nd2 = 0; nd2 < 5; ++nd2) {
                float* oA = o[nd2 * 2];
                float* oB = o[nd2 * 2 + 1];
                const uint32_t cbase = st + 11264 + (uint32_t)(nd2 * 32) + vrow;
                #pragma unroll
                for (int kb = 0; kb < 4; ++kb) {
                    uint32_t v4[4];
                    ldsm4t(v4, cbase + (uint32_t)(kb * 16 * 176));
                    mma16816h(oA, ph[kb], v4[0], v4[1]);
                    mma16816h(oB, ph[kb], v4[2], v4[3]);
                }
            }
        }
        __syncthreads();
    }

    // Epilogue: normalize + write ctx directly as fp16 (row-major [s][D])
    const float inv0 = 1.f / l0, inv1 = 1.f / l1;
    const int r0 = qt * 128 + wm + (lane >> 2);
    #pragma unroll
    for (int nd = 0; nd < 10; ++nd) {
        const int col = h * HD_ + nd * 8 + (lane & 3) * 2;
        *(uint32_t*)&ctxf[((size_t)(b * S_ + r0)) * D_ + col] =
            h2pack(o[nd][0] * inv0, o[nd][1] * inv0);
        *(uint32_t*)&ctxf[((size_t)(b * S_ + r0 + 8)) * D_ + col] =
            h2pack(o[nd][2] * inv1, o[nd][3] * inv1);
    }
}

// ---------------------------------------------------------------------------
// Launch
// ---------------------------------------------------------------------------
extern "C" void kernel_launch(void* const* d_in, const int* in_sizes, int n_in,
                              void* d_out, int out_size)
{
    const float* x      = (const float*)d_in[0];
    const float* wqkv_w = (const float*)d_in[1];
    const float* wqkv_b = (const float*)d_in[2];
    const float* out_w  = (const float*)d_in[3];
    const float* out_b  = (const float*)d_in[4];
    float* out = (float*)d_out;

    float* qkv;
    __half *xf, *wf, *cf, *of, *qf, *kf, *vf;
    cudaGetSymbolAddress((void**)&qkv, g_qkv);
    cudaGetSymbolAddress((void**)&xf, g_xf);
    cudaGetSymbolAddress((void**)&wf, g_wf);
    cudaGetSymbolAddress((void**)&cf, g_cf);
    cudaGetSymbolAddress((void**)&of, g_of);
    cudaGetSymbolAddress((void**)&qf, g_qf);
    cudaGetSymbolAddress((void**)&kf, g_kf);
    cudaGetSymbolAddress((void**)&vf, g_vf);

    cudaFuncSetAttribute(gemm_fp16,
                         cudaFuncAttributeMaxDynamicSharedMemorySize, GEMMH_SMEM);
    cudaFuncSetAttribute(attn_tc,
                         cudaFuncAttributeMaxDynamicSharedMemorySize, ATTN_SMEM);

    // 0) rope table + fp16 converts
    rope_table_kernel<<<S_ * 16 / 256, 256>>>();
    {
        const int n4x = M_ROWS * D_ / 4;
        cvt_h<<<n4x / 256, 256>>>((const float4*)x, (uint2*)xf, n4x);
        const int n4w = QKV_N * D_ / 4;
        cvt_h<<<n4w / 256, 256>>>((const float4*)wqkv_w, (uint2*)wf, n4w);
        const int n4o = D_ * D_ / 4;
        cvt_h<<<n4o / 256, 256>>>((const float4*)out_w, (uint2*)of, n4o);
    }

    // 1) QKV = X @ Wqkv^T + b   (fp16 single-pass)
    dim3 g1(QKV_N / 128, M_ROWS / 128);
    gemm_fp16<<<g1, 256, GEMMH_SMEM>>>(xf, wf, wqkv_b, qkv, M_ROWS, QKV_N, D_);

    // 2) fused RoPE(table) + scale + convert qkv -> head-major fp16
    cvt_qkv<<<(M_ROWS * QKV_N / 4) / 256, 256>>>((const float4*)qkv);

    // 3) causal attention (fp16) -> ctx (fp16)
    dim3 ga(S_ / 128, H_, B_);
    attn_tc<<<ga, 256, ATTN_SMEM>>>(qf, kf, vf, cf);

    // 4) out = ctx @ Wout^T + b   (fp16 single-pass)
    dim3 g2(D_ / 128, M_ROWS / 128);
    gemm_fp16<<<g2, 256, GEMMH_SMEM>>>(cf, of, out_b, out, M_ROWS, D_, D_);
}